// round 1
// baseline (speedup 1.0000x reference)
#include <cuda_runtime.h>

#define NH   16
#define NKV  4
#define HD   64
#define DM   1024
#define BB   2
#define SEQ  2048
#define MROWS (BB*SEQ)   // 4096

// Scratch (allocation-free: static device globals)
__device__ float g_q[(size_t)MROWS * DM];          // (b,n,16,64)
__device__ float g_k[(size_t)MROWS * NKV * HD];    // (b,n,4,64)
__device__ float g_v[(size_t)MROWS * NKV * HD];    // (b,n,4,64)
__device__ float g_attn[(size_t)MROWS * DM];       // (b,n,1024)

// ---------------------------------------------------------------------------
// Generic 128x128x8 SGEMM tile, 256 threads, 8x8 microtile.
// A: row-major (lda == K), B: row-major KxN (ldb), C: row-major (ldc).
// ---------------------------------------------------------------------------
__device__ __forceinline__ void gemm_tile(
    const float* __restrict__ A, const float* __restrict__ B, float* __restrict__ C,
    int K, int ldb, int ldc, int n0, int row0)
{
    __shared__ float As[8][128];
    __shared__ float Bs[8][128];
    const int tid = threadIdx.x;
    const int tx = tid & 15, ty = tid >> 4;
    const int aRow = tid >> 1, aCol = (tid & 1) << 2;
    const int bRow = tid >> 5, bCol = (tid & 31) << 2;

    float acc[8][8];
#pragma unroll
    for (int i = 0; i < 8; i++)
#pragma unroll
        for (int j = 0; j < 8; j++) acc[i][j] = 0.f;

    const float* Aptr = A + (size_t)(row0 + aRow) * K + aCol;
    const float* Bptr = B + (size_t)bRow * ldb + n0 + bCol;

    for (int k0 = 0; k0 < K; k0 += 8) {
        float4 av = *(const float4*)(Aptr + k0);
        As[aCol + 0][aRow] = av.x;
        As[aCol + 1][aRow] = av.y;
        As[aCol + 2][aRow] = av.z;
        As[aCol + 3][aRow] = av.w;
        *(float4*)&Bs[bRow][bCol] = *(const float4*)(Bptr + (size_t)k0 * ldb);
        __syncthreads();
#pragma unroll
        for (int kk = 0; kk < 8; kk++) {
            float a[8], b[8];
            *(float4*)&a[0] = *(const float4*)&As[kk][ty * 8];
            *(float4*)&a[4] = *(const float4*)&As[kk][ty * 8 + 4];
            *(float4*)&b[0] = *(const float4*)&Bs[kk][tx * 8];
            *(float4*)&b[4] = *(const float4*)&Bs[kk][tx * 8 + 4];
#pragma unroll
            for (int i = 0; i < 8; i++)
#pragma unroll
                for (int j = 0; j < 8; j++) acc[i][j] = fmaf(a[i], b[j], acc[i][j]);
        }
        __syncthreads();
    }
#pragma unroll
    for (int i = 0; i < 8; i++) {
        float4 v0 = make_float4(acc[i][0], acc[i][1], acc[i][2], acc[i][3]);
        float4 v1 = make_float4(acc[i][4], acc[i][5], acc[i][6], acc[i][7]);
        float* cp = C + (size_t)(row0 + ty * 8 + i) * ldc + n0 + tx * 8;
        *(float4*)cp = v0;
        *(float4*)(cp + 4) = v1;
    }
}

// Fused QKV projection: grid (12, 32). Tiles 0..7 -> Q, 8..9 -> K, 10..11 -> V.
__global__ __launch_bounds__(256) void qkv_gemm(
    const float* __restrict__ x,
    const float* __restrict__ Wq, const float* __restrict__ Wk, const float* __restrict__ Wv)
{
    int bx = blockIdx.x, row0 = blockIdx.y * 128;
    if (bx < 8)       gemm_tile(x, Wq, g_q, DM, DM,  DM,  bx * 128,        row0);
    else if (bx < 10) gemm_tile(x, Wk, g_k, DM, 256, 256, (bx - 8) * 128,  row0);
    else              gemm_tile(x, Wv, g_v, DM, 256, 256, (bx - 10) * 128, row0);
}

// Output projection: grid (8, 32)
__global__ __launch_bounds__(256) void out_gemm(const float* __restrict__ Wo, float* __restrict__ out)
{
    gemm_tile(g_attn, Wo, out, DM, DM, DM, blockIdx.x * 128, blockIdx.y * 128);
}

// ---------------------------------------------------------------------------
// RoPE, exact reference semantics: t1=t[::2], t2=t[1::2];
// out[0:32]=t1*c - t2*s ; out[32:64]=t1*s + t2*c.  One warp per 64-elem row.
// Handles q rows first (H=16), then k rows (H=4). In-place.
// ---------------------------------------------------------------------------
__global__ void rope_kernel(const float* __restrict__ cs, const float* __restrict__ sn)
{
    int g = blockIdx.x * blockDim.x + threadIdx.x;
    int w = g >> 5;
    int lane = g & 31;
    float* p; int n;
    if (w < MROWS * NH) {
        p = g_q + (size_t)w * HD;
        n = (w >> 4) & (SEQ - 1);      // row = (b*SEQ+n)*16 + h
    } else {
        int w2 = w - MROWS * NH;
        p = g_k + (size_t)w2 * HD;
        n = (w2 >> 2) & (SEQ - 1);     // row = (b*SEQ+n)*4 + kvh
    }
    float e  = p[2 * lane];
    float od = p[2 * lane + 1];
    float c = cs[n * (HD / 2) + lane];
    float s = sn[n * (HD / 2) + lane];
    __syncwarp();
    p[lane]      = e * c - od * s;
    p[lane + 32] = e * s + od * c;
}

// ---------------------------------------------------------------------------
// Flash attention: BM=128 q rows per block, BN=64 k cols per iter, 128 threads,
// 8x8 microtiles for S and PV. GQA: head h uses kv head h>>2. Non-causal.
// Dynamic smem: Qs 128x65 | Ks 64x65 | Vs 64x65 | Ps 128x65 = 99840 B.
// ---------------------------------------------------------------------------
__global__ __launch_bounds__(128, 2) void attn_kernel()
{
    extern __shared__ float sm_[];
    float* Qs = sm_;                 // [128][65]
    float* Ks = Qs + 128 * 65;       // [64][65]
    float* Vs = Ks + 64 * 65;        // [64][65]
    float* Ps = Vs + 64 * 65;        // [128][65]

    const int b = blockIdx.z, h = blockIdx.y;
    const int n0 = blockIdx.x * 128;
    const int kvh = h >> 2;
    const int tid = threadIdx.x;
    const int tx = tid & 7, ty = tid >> 3;   // 16 row-groups x 8 col-groups
    const int lr = tid >> 4;                 // loader row 0..7
    const int lc = (tid & 15) << 2;          // loader col (float4) 0..60

    // Load + pre-scale Q tile (scale = HD^-0.5 = 0.125)
#pragma unroll
    for (int p = 0; p < 16; p++) {
        int r = p * 8 + lr;
        float4 vq = *(const float4*)&g_q[(((size_t)b * SEQ + n0 + r) * NH + h) * HD + lc];
        float* dq = &Qs[r * 65 + lc];
        dq[0] = vq.x * 0.125f; dq[1] = vq.y * 0.125f;
        dq[2] = vq.z * 0.125f; dq[3] = vq.w * 0.125f;
    }

    float m[8], l[8], o[8][8];
#pragma unroll
    for (int i = 0; i < 8; i++) {
        m[i] = -1e30f; l[i] = 0.f;
#pragma unroll
        for (int j = 0; j < 8; j++) o[i][j] = 0.f;
    }

    for (int kt = 0; kt < SEQ / 64; kt++) {
        __syncthreads();   // previous iter's PV readers done (also covers Qs fill on iter 0)
        const int c0 = kt * 64;
#pragma unroll
        for (int p = 0; p < 8; p++) {
            int r = p * 8 + lr;
            size_t base = (((size_t)b * SEQ + c0 + r) * NKV + kvh) * HD + lc;
            float4 kv = *(const float4*)&g_k[base];
            float* dk = &Ks[r * 65 + lc];
            dk[0] = kv.x; dk[1] = kv.y; dk[2] = kv.z; dk[3] = kv.w;
            float4 vv = *(const float4*)&g_v[base];
            float* dv = &Vs[r * 65 + lc];
            dv[0] = vv.x; dv[1] = vv.y; dv[2] = vv.z; dv[3] = vv.w;
        }
        __syncthreads();

        // S = Qs(128x64) * Ks(64x64)^T  -> thread owns 8x8
        float s[8][8];
#pragma unroll
        for (int i = 0; i < 8; i++)
#pragma unroll
            for (int j = 0; j < 8; j++) s[i][j] = 0.f;
#pragma unroll 4
        for (int d = 0; d < 64; d++) {
            float qa[8], kb[8];
#pragma unroll
            for (int i = 0; i < 8; i++) qa[i] = Qs[(ty * 8 + i) * 65 + d];
#pragma unroll
            for (int j = 0; j < 8; j++) kb[j] = Ks[(tx * 8 + j) * 65 + d];
#pragma unroll
            for (int i = 0; i < 8; i++)
#pragma unroll
                for (int j = 0; j < 8; j++) s[i][j] = fmaf(qa[i], kb[j], s[i][j]);
        }

        // Online softmax per row; row spread across 8 tx lanes (xor 1,2,4)
#pragma unroll
        for (int i = 0; i < 8; i++) {
            float mx = s[i][0];
#pragma unroll
            for (int j = 1; j < 8; j++) mx = fmaxf(mx, s[i][j]);
            mx = fmaxf(mx, __shfl_xor_sync(0xffffffffu, mx, 1));
            mx = fmaxf(mx, __shfl_xor_sync(0xffffffffu, mx, 2));
            mx = fmaxf(mx, __shfl_xor_sync(0xffffffffu, mx, 4));
            float mn = fmaxf(m[i], mx);
            float corr = __expf(m[i] - mn);
            m[i] = mn;
            float rs = 0.f;
#pragma unroll
            for (int j = 0; j < 8; j++) { s[i][j] = __expf(s[i][j] - mn); rs += s[i][j]; }
            rs += __shfl_xor_sync(0xffffffffu, rs, 1);
            rs += __shfl_xor_sync(0xffffffffu, rs, 2);
            rs += __shfl_xor_sync(0xffffffffu, rs, 4);
            l[i] = l[i] * corr + rs;
#pragma unroll
            for (int j = 0; j < 8; j++) {
                o[i][j] *= corr;
                Ps[(ty * 8 + i) * 65 + tx * 8 + j] = s[i][j];
            }
        }
        __syncthreads();

        // O += Ps(128x64) * Vs(64x64)
#pragma unroll 2
        for (int c = 0; c < 64; c++) {
            float pa[8], vb[8];
#pragma unroll
            for (int i = 0; i < 8; i++) pa[i] = Ps[(ty * 8 + i) * 65 + c];
#pragma unroll
            for (int j = 0; j < 8; j++) vb[j] = Vs[c * 65 + tx * 8 + j];
#pragma unroll
            for (int i = 0; i < 8; i++)
#pragma unroll
                for (int j = 0; j < 8; j++) o[i][j] = fmaf(pa[i], vb[j], o[i][j]);
        }
    }

    // Epilogue: normalize, write to (b,n,1024) layout for the Wo GEMM
#pragma unroll
    for (int i = 0; i < 8; i++) {
        float inv = 1.f / l[i];
        float* op = &g_attn[((size_t)(b * SEQ + n0 + ty * 8 + i)) * DM + h * HD + tx * 8];
        float4 v0 = make_float4(o[i][0] * inv, o[i][1] * inv, o[i][2] * inv, o[i][3] * inv);
        float4 v1 = make_float4(o[i][4] * inv, o[i][5] * inv, o[i][6] * inv, o[i][7] * inv);
        *(float4*)op = v0;
        *(float4*)(op + 4) = v1;
    }
}

// ---------------------------------------------------------------------------
extern "C" void kernel_launch(void* const* d_in, const int* in_sizes, int n_in,
                              void* d_out, int out_size)
{
    const float* x  = (const float*)d_in[0];
    const float* cs = (const float*)d_in[1];
    const float* sn = (const float*)d_in[2];
    const float* Wq = (const float*)d_in[3];
    const float* Wk = (const float*)d_in[4];
    const float* Wv = (const float*)d_in[5];
    const float* Wo = (const float*)d_in[6];
    float* out = (float*)d_out;
    (void)in_sizes; (void)n_in; (void)out_size;

    // 99840 B dynamic smem for the attention kernel (idempotent; not a stream op)
    cudaFuncSetAttribute(attn_kernel, cudaFuncAttributeMaxDynamicSharedMemorySize, 99840);

    // 1) QKV projections (fused single launch, 384 blocks)
    qkv_gemm<<<dim3(12, 32), 256>>>(x, Wq, Wk, Wv);

    // 2) RoPE on q (65536 rows) + k (16384 rows): 81920 warps -> 10240 blocks
    rope_kernel<<<10240, 256>>>(cs, sn);

    // 3) Attention: grid (16 q-tiles, 16 heads, 2 batch)
    attn_kernel<<<dim3(SEQ / 128, NH, BB), 128, 99840>>>();

    // 4) Output projection
    out_gemm<<<dim3(8, 32), 256>>>(Wo, out);
}

// round 2
// speedup vs baseline: 2.8084x; 2.8084x over previous
#include <cuda_runtime.h>
#include <cstdint>

#define NH   16
#define NKV  4
#define HD   64
#define DM   1024
#define BB   2
#define SEQ  2048
#define MROWS (BB*SEQ)   // 4096

// Scratch (allocation-free: static device globals)
__device__ float g_q[(size_t)MROWS * DM];          // (b,n,16,64)
__device__ float g_k[(size_t)MROWS * NKV * HD];    // (b,n,4,64)
__device__ float g_v[(size_t)MROWS * NKV * HD];    // (b,n,4,64)
__device__ float g_attn[(size_t)MROWS * DM];       // (b,n,1024)

// ---------------------------------------------------------------------------
// tf32 helpers
// ---------------------------------------------------------------------------
__device__ __forceinline__ uint32_t f2tf(float f) {
    uint32_t u;
    asm("cvt.rna.tf32.f32 %0, %1;" : "=r"(u) : "f"(f));
    return u;
}

// D += A*B for m16n8k8 tf32 (row.col), fp32 accum.
// A frag: a0=(g,t) a1=(g+8,t) a2=(g,t+4) a3=(g+8,t+4)   [g=lane>>2, t=lane&3]
// B frag: b0=(k=t, n=g) b1=(k=t+4, n=g)
// C frag: c0=(g,2t) c1=(g,2t+1) c2=(g+8,2t) c3=(g+8,2t+1)
__device__ __forceinline__ void mma8(float c[4], const uint32_t a[4], const uint32_t b[2]) {
    asm volatile(
        "mma.sync.aligned.m16n8k8.row.col.f32.tf32.tf32.f32 "
        "{%0,%1,%2,%3},{%4,%5,%6,%7},{%8,%9},{%0,%1,%2,%3};"
        : "+f"(c[0]), "+f"(c[1]), "+f"(c[2]), "+f"(c[3])
        : "r"(a[0]), "r"(a[1]), "r"(a[2]), "r"(a[3]), "r"(b[0]), "r"(b[1]));
}

// ---------------------------------------------------------------------------
// tf32 tensor-core SGEMM tile: 128x128 block, kstep 32, 256 threads (8 warps),
// warp tile 64x32 (4 mtiles x 4 ntiles of m16n8k8).
// A row-major (lda==K), B row-major KxN (ldb), C row-major (ldc).
// ---------------------------------------------------------------------------
struct SmemGemm {
    uint32_t As[128][36];   // [m][k], pad 4 -> conflict-free frag loads
    uint32_t Bs[32][132];   // [k][n], pad 4
};

__device__ __forceinline__ void gemm_tile_tf32(
    SmemGemm& S,
    const float* __restrict__ A, const float* __restrict__ B, float* __restrict__ C,
    int K, int ldb, int ldc, int n0, int row0)
{
    const int tid  = threadIdx.x;
    const int lane = tid & 31;
    const int wid  = tid >> 5;
    const int g = lane >> 2, t = lane & 3;
    const int m0 = (wid >> 2) * 64;
    const int nw = (wid & 3) * 32;

    float acc[4][4][4];
#pragma unroll
    for (int mi = 0; mi < 4; mi++)
#pragma unroll
        for (int ni = 0; ni < 4; ni++)
#pragma unroll
            for (int r = 0; r < 4; r++) acc[mi][ni][r] = 0.f;

    for (int k0 = 0; k0 < K; k0 += 32) {
        // Load A tile 128x32 (coalesced: 4 rows x 8 float4 per warp)
#pragma unroll
        for (int i = 0; i < 4; i++) {
            int idx = tid + i * 256;
            int r = idx >> 3, c = (idx & 7) << 2;
            float4 v = *(const float4*)(A + (size_t)(row0 + r) * K + k0 + c);
            uint32_t* d = &S.As[r][c];
            d[0] = f2tf(v.x); d[1] = f2tf(v.y); d[2] = f2tf(v.z); d[3] = f2tf(v.w);
        }
        // Load B tile 32x128 (coalesced: 1 k-row x 512B per warp)
#pragma unroll
        for (int i = 0; i < 4; i++) {
            int idx = tid + i * 256;
            int kk = idx >> 5, n4 = (idx & 31) << 2;
            float4 v = *(const float4*)(B + (size_t)(k0 + kk) * ldb + n0 + n4);
            uint32_t* d = &S.Bs[kk][n4];
            d[0] = f2tf(v.x); d[1] = f2tf(v.y); d[2] = f2tf(v.z); d[3] = f2tf(v.w);
        }
        __syncthreads();

#pragma unroll
        for (int kk0 = 0; kk0 < 32; kk0 += 8) {
            uint32_t a[4][4], b[4][2];
#pragma unroll
            for (int mi = 0; mi < 4; mi++) {
                int rb = m0 + mi * 16 + g;
                a[mi][0] = S.As[rb][kk0 + t];
                a[mi][1] = S.As[rb + 8][kk0 + t];
                a[mi][2] = S.As[rb][kk0 + t + 4];
                a[mi][3] = S.As[rb + 8][kk0 + t + 4];
            }
#pragma unroll
            for (int ni = 0; ni < 4; ni++) {
                b[ni][0] = S.Bs[kk0 + t][nw + ni * 8 + g];
                b[ni][1] = S.Bs[kk0 + t + 4][nw + ni * 8 + g];
            }
#pragma unroll
            for (int mi = 0; mi < 4; mi++)
#pragma unroll
                for (int ni = 0; ni < 4; ni++)
                    mma8(acc[mi][ni], a[mi], b[ni]);
        }
        __syncthreads();
    }

    // Epilogue
#pragma unroll
    for (int mi = 0; mi < 4; mi++) {
        int r = row0 + m0 + mi * 16 + g;
#pragma unroll
        for (int ni = 0; ni < 4; ni++) {
            int c = n0 + nw + ni * 8 + 2 * t;
            *(float2*)(C + (size_t)r * ldc + c)       = make_float2(acc[mi][ni][0], acc[mi][ni][1]);
            *(float2*)(C + (size_t)(r + 8) * ldc + c) = make_float2(acc[mi][ni][2], acc[mi][ni][3]);
        }
    }
}

// Fused QKV projection: grid (12, 32). Tiles 0..7 -> Q, 8..9 -> K, 10..11 -> V.
__global__ __launch_bounds__(256) void qkv_gemm(
    const float* __restrict__ x,
    const float* __restrict__ Wq, const float* __restrict__ Wk, const float* __restrict__ Wv)
{
    __shared__ SmemGemm S;
    int bx = blockIdx.x, row0 = blockIdx.y * 128;
    if (bx < 8)       gemm_tile_tf32(S, x, Wq, g_q, DM, DM,  DM,  bx * 128,        row0);
    else if (bx < 10) gemm_tile_tf32(S, x, Wk, g_k, DM, 256, 256, (bx - 8) * 128,  row0);
    else              gemm_tile_tf32(S, x, Wv, g_v, DM, 256, 256, (bx - 10) * 128, row0);
}

// Output projection: grid (8, 32)
__global__ __launch_bounds__(256) void out_gemm(const float* __restrict__ Wo, float* __restrict__ out)
{
    __shared__ SmemGemm S;
    gemm_tile_tf32(S, g_attn, Wo, out, DM, DM, DM, blockIdx.x * 128, blockIdx.y * 128);
}

// ---------------------------------------------------------------------------
// RoPE (exact reference semantics), one warp per 64-elem head row, in-place.
// ---------------------------------------------------------------------------
__global__ void rope_kernel(const float* __restrict__ cs, const float* __restrict__ sn)
{
    int gidx = blockIdx.x * blockDim.x + threadIdx.x;
    int w = gidx >> 5;
    int lane = gidx & 31;
    float* p; int n;
    if (w < MROWS * NH) {
        p = g_q + (size_t)w * HD;
        n = (w >> 4) & (SEQ - 1);
    } else {
        int w2 = w - MROWS * NH;
        p = g_k + (size_t)w2 * HD;
        n = (w2 >> 2) & (SEQ - 1);
    }
    float e  = p[2 * lane];
    float od = p[2 * lane + 1];
    float c = cs[n * (HD / 2) + lane];
    float s = sn[n * (HD / 2) + lane];
    __syncwarp();
    p[lane]      = e * c - od * s;
    p[lane + 32] = e * s + od * c;
}

// ---------------------------------------------------------------------------
// Flash attention with tf32 mma. 256 threads = 8 warps.
// BM=128 q rows (warp w owns rows w*16..w*16+15), BN=64 keys/iter.
// S: per warp 1 mtile x 8 ntiles; softmax rows fully warp-local.
// P staged through smem (tf32) -> PV mma, o accum 16 rows x 64 d per warp.
// Smem: Qs[128][68] Ks[64][68] Vs[64][68] Ps[128][68] (u32) = 104448 B.
// ---------------------------------------------------------------------------
__global__ __launch_bounds__(256) void attn_mma()
{
    extern __shared__ uint32_t sm_[];
    uint32_t* Qs = sm_;               // [128][68]
    uint32_t* Ks = Qs + 128 * 68;     // [64][68]
    uint32_t* Vs = Ks + 64 * 68;      // [64][68]
    uint32_t* Ps = Vs + 64 * 68;      // [128][68]

    const int b = blockIdx.z, h = blockIdx.y;
    const int n0 = blockIdx.x * 128;
    const int kvh = h >> 2;
    const int tid = threadIdx.x;
    const int lane = tid & 31;
    const int wid = tid >> 5;
    const int g = lane >> 2, t = lane & 3;
    const int m0 = wid * 16;

    // Load + pre-scale Q tile (scale = 0.125), convert to tf32
#pragma unroll
    for (int i = 0; i < 8; i++) {
        int idx = tid + i * 256;
        int r = idx >> 4, c4 = (idx & 15) << 2;
        float4 v = *(const float4*)&g_q[(((size_t)b * SEQ + n0 + r) * NH + h) * HD + c4];
        uint32_t* d = &Qs[r * 68 + c4];
        d[0] = f2tf(v.x * 0.125f); d[1] = f2tf(v.y * 0.125f);
        d[2] = f2tf(v.z * 0.125f); d[3] = f2tf(v.w * 0.125f);
    }

    float m0s = -1e30f, m1s = -1e30f, l0s = 0.f, l1s = 0.f;
    float o[8][4];
#pragma unroll
    for (int ni = 0; ni < 8; ni++)
#pragma unroll
        for (int r = 0; r < 4; r++) o[ni][r] = 0.f;

    for (int kt = 0; kt < SEQ / 64; kt++) {
        __syncthreads();   // prior PV readers of Ks/Vs/Ps done; Qs fill done (iter 0)
        const int c0 = kt * 64;
#pragma unroll
        for (int i = 0; i < 4; i++) {
            int idx = tid + i * 256;
            int r = idx >> 4, c4 = (idx & 15) << 2;
            size_t base = (((size_t)b * SEQ + c0 + r) * NKV + kvh) * HD + c4;
            float4 kv = *(const float4*)&g_k[base];
            uint32_t* dk = &Ks[r * 68 + c4];
            dk[0] = f2tf(kv.x); dk[1] = f2tf(kv.y); dk[2] = f2tf(kv.z); dk[3] = f2tf(kv.w);
            float4 vv = *(const float4*)&g_v[base];
            uint32_t* dv = &Vs[r * 68 + c4];
            dv[0] = f2tf(vv.x); dv[1] = f2tf(vv.y); dv[2] = f2tf(vv.z); dv[3] = f2tf(vv.w);
        }
        __syncthreads();

        // S = Q * K^T : warp computes rows m0..m0+15 x 64 keys
        float s[8][4];
#pragma unroll
        for (int ni = 0; ni < 8; ni++)
#pragma unroll
            for (int r = 0; r < 4; r++) s[ni][r] = 0.f;
#pragma unroll
        for (int kk0 = 0; kk0 < 64; kk0 += 8) {
            uint32_t a[4];
            a[0] = Qs[(m0 + g) * 68 + kk0 + t];
            a[1] = Qs[(m0 + g + 8) * 68 + kk0 + t];
            a[2] = Qs[(m0 + g) * 68 + kk0 + t + 4];
            a[3] = Qs[(m0 + g + 8) * 68 + kk0 + t + 4];
#pragma unroll
            for (int ni = 0; ni < 8; ni++) {
                uint32_t bb[2];
                bb[0] = Ks[(ni * 8 + g) * 68 + kk0 + t];
                bb[1] = Ks[(ni * 8 + g) * 68 + kk0 + t + 4];
                mma8(s[ni], a, bb);
            }
        }

        // Online softmax. Thread owns cols {2t,2t+1} of rows (m0+g) [c0,c1]
        // and (m0+g+8) [c2,c3]; reduce across t via shfl xor 1,2.
        float mx0 = -1e30f, mx1 = -1e30f;
#pragma unroll
        for (int ni = 0; ni < 8; ni++) {
            mx0 = fmaxf(mx0, fmaxf(s[ni][0], s[ni][1]));
            mx1 = fmaxf(mx1, fmaxf(s[ni][2], s[ni][3]));
        }
        mx0 = fmaxf(mx0, __shfl_xor_sync(0xffffffffu, mx0, 1));
        mx0 = fmaxf(mx0, __shfl_xor_sync(0xffffffffu, mx0, 2));
        mx1 = fmaxf(mx1, __shfl_xor_sync(0xffffffffu, mx1, 1));
        mx1 = fmaxf(mx1, __shfl_xor_sync(0xffffffffu, mx1, 2));

        float mn0 = fmaxf(m0s, mx0), mn1 = fmaxf(m1s, mx1);
        float cor0 = __expf(m0s - mn0), cor1 = __expf(m1s - mn1);
        m0s = mn0; m1s = mn1;

        float rs0 = 0.f, rs1 = 0.f;
#pragma unroll
        for (int ni = 0; ni < 8; ni++) {
            float e0 = __expf(s[ni][0] - mn0);
            float e1 = __expf(s[ni][1] - mn0);
            float e2 = __expf(s[ni][2] - mn1);
            float e3 = __expf(s[ni][3] - mn1);
            rs0 += e0 + e1; rs1 += e2 + e3;
            Ps[(m0 + g) * 68 + ni * 8 + 2 * t]         = f2tf(e0);
            Ps[(m0 + g) * 68 + ni * 8 + 2 * t + 1]     = f2tf(e1);
            Ps[(m0 + g + 8) * 68 + ni * 8 + 2 * t]     = f2tf(e2);
            Ps[(m0 + g + 8) * 68 + ni * 8 + 2 * t + 1] = f2tf(e3);
        }
        rs0 += __shfl_xor_sync(0xffffffffu, rs0, 1);
        rs0 += __shfl_xor_sync(0xffffffffu, rs0, 2);
        rs1 += __shfl_xor_sync(0xffffffffu, rs1, 1);
        rs1 += __shfl_xor_sync(0xffffffffu, rs1, 2);
        l0s = l0s * cor0 + rs0;
        l1s = l1s * cor1 + rs1;

#pragma unroll
        for (int ni = 0; ni < 8; ni++) {
            o[ni][0] *= cor0; o[ni][1] *= cor0;
            o[ni][2] *= cor1; o[ni][3] *= cor1;
        }
        __syncthreads();   // Ps visible to all (warp-local actually, but keep tile order)

        // O += P * V : A = Ps (k = key), B = Vs (k x d)
#pragma unroll
        for (int kk0 = 0; kk0 < 64; kk0 += 8) {
            uint32_t a[4];
            a[0] = Ps[(m0 + g) * 68 + kk0 + t];
            a[1] = Ps[(m0 + g + 8) * 68 + kk0 + t];
            a[2] = Ps[(m0 + g) * 68 + kk0 + t + 4];
            a[3] = Ps[(m0 + g + 8) * 68 + kk0 + t + 4];
#pragma unroll
            for (int ni = 0; ni < 8; ni++) {
                uint32_t bb[2];
                bb[0] = Vs[(kk0 + t) * 68 + ni * 8 + g];
                bb[1] = Vs[(kk0 + t + 4) * 68 + ni * 8 + g];
                mma8(o[ni], a, bb);
            }
        }
    }

    // Epilogue: normalize, write (b,n,1024) layout for Wo GEMM
    float inv0 = 1.f / l0s, inv1 = 1.f / l1s;
    size_t r0 = (size_t)b * SEQ + n0 + m0 + g;
#pragma unroll
    for (int ni = 0; ni < 8; ni++) {
        int col = h * HD + ni * 8 + 2 * t;
        *(float2*)&g_attn[r0 * DM + col]       = make_float2(o[ni][0] * inv0, o[ni][1] * inv0);
        *(float2*)&g_attn[(r0 + 8) * DM + col] = make_float2(o[ni][2] * inv1, o[ni][3] * inv1);
    }
}

// ---------------------------------------------------------------------------
extern "C" void kernel_launch(void* const* d_in, const int* in_sizes, int n_in,
                              void* d_out, int out_size)
{
    const float* x  = (const float*)d_in[0];
    const float* cs = (const float*)d_in[1];
    const float* sn = (const float*)d_in[2];
    const float* Wq = (const float*)d_in[3];
    const float* Wk = (const float*)d_in[4];
    const float* Wv = (const float*)d_in[5];
    const float* Wo = (const float*)d_in[6];
    float* out = (float*)d_out;
    (void)in_sizes; (void)n_in; (void)out_size;

    cudaFuncSetAttribute(attn_mma, cudaFuncAttributeMaxDynamicSharedMemorySize, 104448);

    // 1) QKV projections
    qkv_gemm<<<dim3(12, 32), 256>>>(x, Wq, Wk, Wv);

    // 2) RoPE on q + k rows: 81920 warps -> 10240 blocks
    rope_kernel<<<10240, 256>>>(cs, sn);

    // 3) Attention: grid (16 q-tiles, 16 heads, 2 batch)
    attn_mma<<<dim3(SEQ / 128, NH, BB), 256, 104448>>>();

    // 4) Output projection
    out_gemm<<<dim3(8, 32), 256>>>(Wo, out);
}

// round 3
// speedup vs baseline: 3.4426x; 1.2258x over previous
#include <cuda_runtime.h>
#include <cstdint>

#define NH   16
#define NKV  4
#define HD   64
#define DM   1024
#define BB   2
#define SEQ  2048
#define MROWS (BB*SEQ)   // 4096

// Scratch (allocation-free: static device globals)
__device__ float g_q[(size_t)MROWS * DM];          // (b,n,16,64)
__device__ float g_k[(size_t)MROWS * NKV * HD];    // (b,n,4,64)
__device__ float g_v[(size_t)MROWS * NKV * HD];    // (b,n,4,64)
__device__ float g_attn[(size_t)MROWS * DM];       // (b,n,1024)

// ---------------------------------------------------------------------------
// tf32 helpers
// ---------------------------------------------------------------------------
__device__ __forceinline__ uint32_t f2tf(float f) {
    uint32_t u;
    asm("cvt.rna.tf32.f32 %0, %1;" : "=r"(u) : "f"(f));
    return u;
}

// D += A*B for m16n8k8 tf32 (row.col), fp32 accum.
// A frag: a0=(g,t) a1=(g+8,t) a2=(g,t+4) a3=(g+8,t+4)   [g=lane>>2, t=lane&3]
// B frag: b0=(k=t, n=g) b1=(k=t+4, n=g)
// C frag: c0=(g,2t) c1=(g,2t+1) c2=(g+8,2t) c3=(g+8,2t+1)
__device__ __forceinline__ void mma8(float c[4], const uint32_t a[4], const uint32_t b[2]) {
    asm volatile(
        "mma.sync.aligned.m16n8k8.row.col.f32.tf32.tf32.f32 "
        "{%0,%1,%2,%3},{%4,%5,%6,%7},{%8,%9},{%0,%1,%2,%3};"
        : "+f"(c[0]), "+f"(c[1]), "+f"(c[2]), "+f"(c[3])
        : "r"(a[0]), "r"(a[1]), "r"(a[2]), "r"(a[3]), "r"(b[0]), "r"(b[1]));
}

// ---------------------------------------------------------------------------
// tf32 SGEMM tile: 128x128 block, kstep 64, 256 threads (8 warps),
// warp tile 64x32 (4 mtiles x 4 ntiles of m16n8k8).
// As[128][68] (bank 4g+t conflict-free), Bs[64][136] (bank 8t+g conflict-free)
// Dynamic smem: (128*68 + 64*136) * 4 = 69632 B.
// ---------------------------------------------------------------------------
#define GEMM_SMEM 69632

__device__ __forceinline__ void gemm_tile_tf32(
    uint32_t* sm,
    const float* __restrict__ A, const float* __restrict__ B, float* __restrict__ C,
    int K, int ldb, int ldc, int n0, int row0)
{
    uint32_t (*As)[68]  = (uint32_t(*)[68])sm;
    uint32_t (*Bs)[136] = (uint32_t(*)[136])(sm + 128 * 68);

    const int tid  = threadIdx.x;
    const int lane = tid & 31;
    const int wid  = tid >> 5;
    const int g = lane >> 2, t = lane & 3;
    const int m0 = (wid >> 2) * 64;
    const int nw = (wid & 3) * 32;

    float acc[4][4][4];
#pragma unroll
    for (int mi = 0; mi < 4; mi++)
#pragma unroll
        for (int ni = 0; ni < 4; ni++)
#pragma unroll
            for (int r = 0; r < 4; r++) acc[mi][ni][r] = 0.f;

    for (int k0 = 0; k0 < K; k0 += 64) {
        // Load A tile 128x64
#pragma unroll
        for (int i = 0; i < 8; i++) {
            int idx = tid + i * 256;
            int r = idx >> 4, c = (idx & 15) << 2;
            float4 v = *(const float4*)(A + (size_t)(row0 + r) * K + k0 + c);
            uint32_t* d = &As[r][c];
            d[0] = f2tf(v.x); d[1] = f2tf(v.y); d[2] = f2tf(v.z); d[3] = f2tf(v.w);
        }
        // Load B tile 64x128
#pragma unroll
        for (int i = 0; i < 8; i++) {
            int idx = tid + i * 256;
            int kk = idx >> 5, n4 = (idx & 31) << 2;
            float4 v = *(const float4*)(B + (size_t)(k0 + kk) * ldb + n0 + n4);
            uint32_t* d = &Bs[kk][n4];
            d[0] = f2tf(v.x); d[1] = f2tf(v.y); d[2] = f2tf(v.z); d[3] = f2tf(v.w);
        }
        __syncthreads();

#pragma unroll
        for (int kk0 = 0; kk0 < 64; kk0 += 8) {
            uint32_t a[4][4], b[4][2];
#pragma unroll
            for (int mi = 0; mi < 4; mi++) {
                int rb = m0 + mi * 16 + g;
                a[mi][0] = As[rb][kk0 + t];
                a[mi][1] = As[rb + 8][kk0 + t];
                a[mi][2] = As[rb][kk0 + t + 4];
                a[mi][3] = As[rb + 8][kk0 + t + 4];
            }
#pragma unroll
            for (int ni = 0; ni < 4; ni++) {
                b[ni][0] = Bs[kk0 + t][nw + ni * 8 + g];
                b[ni][1] = Bs[kk0 + t + 4][nw + ni * 8 + g];
            }
#pragma unroll
            for (int mi = 0; mi < 4; mi++)
#pragma unroll
                for (int ni = 0; ni < 4; ni++)
                    mma8(acc[mi][ni], a[mi], b[ni]);
        }
        __syncthreads();
    }

    // Epilogue
#pragma unroll
    for (int mi = 0; mi < 4; mi++) {
        int r = row0 + m0 + mi * 16 + g;
#pragma unroll
        for (int ni = 0; ni < 4; ni++) {
            int c = n0 + nw + ni * 8 + 2 * t;
            *(float2*)(C + (size_t)r * ldc + c)       = make_float2(acc[mi][ni][0], acc[mi][ni][1]);
            *(float2*)(C + (size_t)(r + 8) * ldc + c) = make_float2(acc[mi][ni][2], acc[mi][ni][3]);
        }
    }
}

// Fused QKV projection: grid (12, 32). Tiles 0..7 -> Q, 8..9 -> K, 10..11 -> V.
__global__ __launch_bounds__(256, 2) void qkv_gemm(
    const float* __restrict__ x,
    const float* __restrict__ Wq, const float* __restrict__ Wk, const float* __restrict__ Wv)
{
    extern __shared__ uint32_t smg_[];
    int bx = blockIdx.x, row0 = blockIdx.y * 128;
    if (bx < 8)       gemm_tile_tf32(smg_, x, Wq, g_q, DM, DM,  DM,  bx * 128,        row0);
    else if (bx < 10) gemm_tile_tf32(smg_, x, Wk, g_k, DM, 256, 256, (bx - 8) * 128,  row0);
    else              gemm_tile_tf32(smg_, x, Wv, g_v, DM, 256, 256, (bx - 10) * 128, row0);
}

// Output projection: grid (8, 32)
__global__ __launch_bounds__(256, 2) void out_gemm(const float* __restrict__ Wo, float* __restrict__ out)
{
    extern __shared__ uint32_t smg_[];
    gemm_tile_tf32(smg_, g_attn, Wo, out, DM, DM, DM, blockIdx.x * 128, blockIdx.y * 128);
}

// ---------------------------------------------------------------------------
// RoPE (exact reference semantics), one warp per 64-elem head row, in-place.
// ---------------------------------------------------------------------------
__global__ void rope_kernel(const float* __restrict__ cs, const float* __restrict__ sn)
{
    int gidx = blockIdx.x * blockDim.x + threadIdx.x;
    int w = gidx >> 5;
    int lane = gidx & 31;
    float* p; int n;
    if (w < MROWS * NH) {
        p = g_q + (size_t)w * HD;
        n = (w >> 4) & (SEQ - 1);
    } else {
        int w2 = w - MROWS * NH;
        p = g_k + (size_t)w2 * HD;
        n = (w2 >> 2) & (SEQ - 1);
    }
    float e  = p[2 * lane];
    float od = p[2 * lane + 1];
    float c = cs[n * (HD / 2) + lane];
    float s = sn[n * (HD / 2) + lane];
    __syncwarp();
    p[lane]      = e * c - od * s;
    p[lane + 32] = e * s + od * c;
}

// ---------------------------------------------------------------------------
// Flash attention, tf32 mma, P kept in registers (no Ps smem round-trip).
// 256 threads = 8 warps; warp w owns q rows w*16..w*16+15; BN=64 keys/iter.
//
// Layout tricks:
//  * Qs/Ks store the d-dim permuted within 8-groups: value d=kk*8+t sits at
//    position kk*8+2t, value kk*8+t+4 at kk*8+2t+1 -> a/b frag pairs are one
//    LDS.64 each. ld=72 words -> bank = 8g+2t+c, conflict-free.
//  * Vs stores keys row-permuted: key j -> row (j&~7)+((j&7)>>1)+((j&1)<<2),
//    so the S C-frag (keys 2t,2t+1 per thread) feeds PV A-slots (k=t,t+4)
//    directly from registers.
// Smem: Qs[128][72] + Ks[64][72] + Vs[64][72] = 73728 B (u32).
// ---------------------------------------------------------------------------
#define ATT_SMEM 73728

__global__ __launch_bounds__(256, 2) void attn_mma()
{
    extern __shared__ uint32_t sm_[];
    uint32_t* Qs = sm_;               // [128][72]
    uint32_t* Ks = Qs + 128 * 72;     // [64][72]
    uint32_t* Vs = Ks + 64 * 72;      // [64][72]

    const int b = blockIdx.z, h = blockIdx.y;
    const int n0 = blockIdx.x * 128;
    const int kvh = h >> 2;
    const int tid = threadIdx.x;
    const int lane = tid & 31;
    const int wid = tid >> 5;
    const int g = lane >> 2, t = lane & 3;
    const int m0 = wid * 16;

    // Load + pre-scale Q tile (scale = 0.125), tf32, d-permuted columns
#pragma unroll
    for (int i = 0; i < 8; i++) {
        int idx = tid + i * 256;
        int r = idx >> 4, c4 = (idx & 15) << 2;
        float4 v = *(const float4*)&g_q[(((size_t)b * SEQ + n0 + r) * NH + h) * HD + c4];
        int grp = c4 & ~7, odd = (c4 >> 2) & 1;
        uint32_t* d = &Qs[r * 72 + grp + odd];
        d[0] = f2tf(v.x * 0.125f); d[2] = f2tf(v.y * 0.125f);
        d[4] = f2tf(v.z * 0.125f); d[6] = f2tf(v.w * 0.125f);
    }

    float m0s = -1e30f, m1s = -1e30f, l0s = 0.f, l1s = 0.f;
    float o[8][4];
#pragma unroll
    for (int ni = 0; ni < 8; ni++)
#pragma unroll
        for (int r = 0; r < 4; r++) o[ni][r] = 0.f;

    for (int kt = 0; kt < SEQ / 64; kt++) {
        __syncthreads();   // prior iter's readers of Ks/Vs done (covers Qs fill on iter 0)
        const int c0 = kt * 64;
#pragma unroll
        for (int i = 0; i < 4; i++) {
            int idx = tid + i * 256;
            int r = idx >> 4, c4 = (idx & 15) << 2;
            size_t base = (((size_t)b * SEQ + c0 + r) * NKV + kvh) * HD + c4;
            // K: d-permuted columns
            float4 kv = *(const float4*)&g_k[base];
            int grp = c4 & ~7, odd = (c4 >> 2) & 1;
            uint32_t* dk = &Ks[r * 72 + grp + odd];
            dk[0] = f2tf(kv.x); dk[2] = f2tf(kv.y); dk[4] = f2tf(kv.z); dk[6] = f2tf(kv.w);
            // V: key-permuted rows, natural columns
            float4 vv = *(const float4*)&g_v[base];
            int rv = (r & ~7) + ((r & 7) >> 1) + ((r & 1) << 2);
            uint32_t* dv = &Vs[rv * 72 + c4];
            dv[0] = f2tf(vv.x); dv[1] = f2tf(vv.y); dv[2] = f2tf(vv.z); dv[3] = f2tf(vv.w);
        }
        __syncthreads();

        // S = Q * K^T : warp computes rows m0..m0+15 x 64 keys
        float s[8][4];
#pragma unroll
        for (int ni = 0; ni < 8; ni++)
#pragma unroll
            for (int r = 0; r < 4; r++) s[ni][r] = 0.f;
#pragma unroll
        for (int kk = 0; kk < 8; kk++) {
            uint32_t a[4];
            uint2 p0 = *(const uint2*)&Qs[(m0 + g) * 72 + kk * 8 + 2 * t];
            uint2 p1 = *(const uint2*)&Qs[(m0 + g + 8) * 72 + kk * 8 + 2 * t];
            a[0] = p0.x; a[1] = p1.x; a[2] = p0.y; a[3] = p1.y;
#pragma unroll
            for (int ni = 0; ni < 8; ni++) {
                uint2 bv = *(const uint2*)&Ks[(ni * 8 + g) * 72 + kk * 8 + 2 * t];
                uint32_t bb[2] = {bv.x, bv.y};
                mma8(s[ni], a, bb);
            }
        }

        // Online softmax; rows (m0+g) [s0,s1] and (m0+g+8) [s2,s3], cols 2t,2t+1
        float mx0 = -1e30f, mx1 = -1e30f;
#pragma unroll
        for (int ni = 0; ni < 8; ni++) {
            mx0 = fmaxf(mx0, fmaxf(s[ni][0], s[ni][1]));
            mx1 = fmaxf(mx1, fmaxf(s[ni][2], s[ni][3]));
        }
        mx0 = fmaxf(mx0, __shfl_xor_sync(0xffffffffu, mx0, 1));
        mx0 = fmaxf(mx0, __shfl_xor_sync(0xffffffffu, mx0, 2));
        mx1 = fmaxf(mx1, __shfl_xor_sync(0xffffffffu, mx1, 1));
        mx1 = fmaxf(mx1, __shfl_xor_sync(0xffffffffu, mx1, 2));

        float mn0 = fmaxf(m0s, mx0), mn1 = fmaxf(m1s, mx1);
        float cor0 = __expf(m0s - mn0), cor1 = __expf(m1s - mn1);
        m0s = mn0; m1s = mn1;

        float rs0 = 0.f, rs1 = 0.f;
        uint32_t pf[8][4];   // PV A-frags, straight from registers
#pragma unroll
        for (int ni = 0; ni < 8; ni++) {
            float e0 = __expf(s[ni][0] - mn0);
            float e1 = __expf(s[ni][1] - mn0);
            float e2 = __expf(s[ni][2] - mn1);
            float e3 = __expf(s[ni][3] - mn1);
            rs0 += e0 + e1; rs1 += e2 + e3;
            // A-frag slot map: a0=key 2t(row g), a1=key 2t(row g+8), a2=key 2t+1(g), a3=key 2t+1(g+8)
            pf[ni][0] = f2tf(e0); pf[ni][1] = f2tf(e2);
            pf[ni][2] = f2tf(e1); pf[ni][3] = f2tf(e3);
        }
        rs0 += __shfl_xor_sync(0xffffffffu, rs0, 1);
        rs0 += __shfl_xor_sync(0xffffffffu, rs0, 2);
        rs1 += __shfl_xor_sync(0xffffffffu, rs1, 1);
        rs1 += __shfl_xor_sync(0xffffffffu, rs1, 2);
        l0s = l0s * cor0 + rs0;
        l1s = l1s * cor1 + rs1;

#pragma unroll
        for (int ni = 0; ni < 8; ni++) {
            o[ni][0] *= cor0; o[ni][1] *= cor0;
            o[ni][2] *= cor1; o[ni][3] *= cor1;
        }

        // O += P * V : A = pf[key-group], B from permuted Vs (bank 8t+g, clean)
#pragma unroll
        for (int kk = 0; kk < 8; kk++) {
#pragma unroll
            for (int ni = 0; ni < 8; ni++) {
                uint32_t bb[2];
                bb[0] = Vs[(kk * 8 + t) * 72 + ni * 8 + g];
                bb[1] = Vs[(kk * 8 + t + 4) * 72 + ni * 8 + g];
                mma8(o[ni], pf[kk], bb);
            }
        }
    }

    // Epilogue: normalize, write (b,n,1024) layout for Wo GEMM
    float inv0 = 1.f / l0s, inv1 = 1.f / l1s;
    size_t r0 = (size_t)b * SEQ + n0 + m0 + g;
#pragma unroll
    for (int ni = 0; ni < 8; ni++) {
        int col = h * HD + ni * 8 + 2 * t;
        *(float2*)&g_attn[r0 * DM + col]       = make_float2(o[ni][0] * inv0, o[ni][1] * inv0);
        *(float2*)&g_attn[(r0 + 8) * DM + col] = make_float2(o[ni][2] * inv1, o[ni][3] * inv1);
    }
}

// ---------------------------------------------------------------------------
extern "C" void kernel_launch(void* const* d_in, const int* in_sizes, int n_in,
                              void* d_out, int out_size)
{
    const float* x  = (const float*)d_in[0];
    const float* cs = (const float*)d_in[1];
    const float* sn = (const float*)d_in[2];
    const float* Wq = (const float*)d_in[3];
    const float* Wk = (const float*)d_in[4];
    const float* Wv = (const float*)d_in[5];
    const float* Wo = (const float*)d_in[6];
    float* out = (float*)d_out;
    (void)in_sizes; (void)n_in; (void)out_size;

    cudaFuncSetAttribute(qkv_gemm, cudaFuncAttributeMaxDynamicSharedMemorySize, GEMM_SMEM);
    cudaFuncSetAttribute(out_gemm, cudaFuncAttributeMaxDynamicSharedMemorySize, GEMM_SMEM);
    cudaFuncSetAttribute(attn_mma, cudaFuncAttributeMaxDynamicSharedMemorySize, ATT_SMEM);

    // 1) QKV projections
    qkv_gemm<<<dim3(12, 32), 256, GEMM_SMEM>>>(x, Wq, Wk, Wv);

    // 2) RoPE on q + k rows: 81920 warps -> 10240 blocks
    rope_kernel<<<10240, 256>>>(cs, sn);

    // 3) Attention: grid (16 q-tiles, 16 heads, 2 batch)
    attn_mma<<<dim3(SEQ / 128, NH, BB), 256, ATT_SMEM>>>();

    // 4) Output projection
    out_gemm<<<dim3(8, 32), 256, GEMM_SMEM>>>(Wo, out);
}

// round 4
// speedup vs baseline: 3.8704x; 1.1243x over previous
#include <cuda_runtime.h>
#include <cstdint>

#define NH   16
#define NKV  4
#define HD   64
#define DM   1024
#define BB   2
#define SEQ  2048
#define MROWS (BB*SEQ)   // 4096

// ---------------------------------------------------------------------------
// Scratch (allocation-free device globals)
// ---------------------------------------------------------------------------
__device__ float g_xr [(size_t)MROWS * DM];       // tf32-rounded x
__device__ float g_wqr[(size_t)DM * DM];          // tf32-rounded Wq
__device__ float g_wkr[(size_t)DM * 256];
__device__ float g_wvr[(size_t)DM * 256];
__device__ float g_wor[(size_t)DM * DM];
__device__ float g_q  [(size_t)BB * NH  * SEQ * HD];  // head-major, d-permuted, *0.125, rope'd, tf32
__device__ float g_k  [(size_t)BB * NKV * SEQ * HD];  // head-major, d-permuted, rope'd, tf32
__device__ float g_v  [(size_t)BB * NKV * SEQ * HD];  // head-major, row-permuted, tf32
__device__ float g_attn[(size_t)MROWS * DM];          // (b,n,1024), tf32-rounded

// ---------------------------------------------------------------------------
// helpers
// ---------------------------------------------------------------------------
__device__ __forceinline__ uint32_t f2tf(float f) {
    uint32_t u;
    asm("cvt.rna.tf32.f32 %0, %1;" : "=r"(u) : "f"(f));
    return u;
}
__device__ __forceinline__ float r2f(uint32_t u) { return __uint_as_float(u); }

// position of head-col j under the within-8-group d-permute
__device__ __forceinline__ int perm8p(int j) {
    int u = j & 7;
    return (j & ~7) + ((u < 4) ? 2 * u : 2 * (u - 4) + 1);
}

__device__ __forceinline__ void mma8(float c[4], const uint32_t a[4], const uint32_t b[2]) {
    asm volatile(
        "mma.sync.aligned.m16n8k8.row.col.f32.tf32.tf32.f32 "
        "{%0,%1,%2,%3},{%4,%5,%6,%7},{%8,%9},{%0,%1,%2,%3};"
        : "+f"(c[0]), "+f"(c[1]), "+f"(c[2]), "+f"(c[3])
        : "r"(a[0]), "r"(a[1]), "r"(a[2]), "r"(a[3]), "r"(b[0]), "r"(b[1]));
}

__device__ __forceinline__ void cpa16(uint32_t dst, const void* src) {
    asm volatile("cp.async.cg.shared.global [%0], [%1], 16;" :: "r"(dst), "l"(src) : "memory");
}
#define CPA_COMMIT() asm volatile("cp.async.commit_group;" ::: "memory")

// ---------------------------------------------------------------------------
// Pre-pass: round x + weights to the tf32 grid (values then feed mma raw).
// ---------------------------------------------------------------------------
__global__ void prep_round(const float* __restrict__ x,  const float* __restrict__ Wq,
                           const float* __restrict__ Wk, const float* __restrict__ Wv,
                           const float* __restrict__ Wo)
{
    size_t i = (size_t)blockIdx.x * 256 + threadIdx.x;   // float4 index
    const float* src; float* dst; size_t off;
    if      (i < 1048576) { src = x;  dst = g_xr;  off = i; }
    else if (i < 1310720) { src = Wq; dst = g_wqr; off = i - 1048576; }
    else if (i < 1376256) { src = Wk; dst = g_wkr; off = i - 1310720; }
    else if (i < 1441792) { src = Wv; dst = g_wvr; off = i - 1376256; }
    else                  { src = Wo; dst = g_wor; off = i - 1441792; }
    float4 v = ((const float4*)src)[off];
    v.x = r2f(f2tf(v.x)); v.y = r2f(f2tf(v.y));
    v.z = r2f(f2tf(v.z)); v.w = r2f(f2tf(v.w));
    ((float4*)dst)[off] = v;
}

// ---------------------------------------------------------------------------
// cp.async 3-stage GEMM mainloop: 128x128 tile, kstep 32, 256 threads,
// warp tile 64x32. Stage: As[128][36] + Bs[32][132] = 8832 words.
// ---------------------------------------------------------------------------
#define GSTAGE 8832
#define GEMM_SMEM (3 * GSTAGE * 4)   // 105984 B

__device__ __forceinline__ void gemm_issue(uint32_t smb, int slot,
    const float* __restrict__ A, const float* __restrict__ B,
    int K, int ldb, int n0, int row0, int kt, int tid)
{
    uint32_t base = smb + slot * (GSTAGE * 4);
#pragma unroll
    for (int i = 0; i < 4; i++) {
        int c = tid + i * 256;
        int r = c >> 3, col = (c & 7) << 2;
        cpa16(base + (r * 36 + col) * 4, A + (size_t)(row0 + r) * K + kt * 32 + col);
    }
#pragma unroll
    for (int i = 0; i < 4; i++) {
        int c = tid + i * 256;
        int kk = c >> 5, nn = (c & 31) << 2;
        cpa16(base + (4608 + kk * 132 + nn) * 4, B + (size_t)(kt * 32 + kk) * ldb + n0 + nn);
    }
    CPA_COMMIT();
}

__device__ __forceinline__ void gemm_main(uint32_t* sm, uint32_t smb,
    const float* __restrict__ A, const float* __restrict__ B,
    int ldb, int n0, int row0, float acc[4][4][4])
{
    const int K = DM, KT = DM / 32;
    const int tid = threadIdx.x, lane = tid & 31, wid = tid >> 5;
    const int g = lane >> 2, t = lane & 3;
    const int m0 = (wid >> 2) * 64, nw = (wid & 3) * 32;

#pragma unroll
    for (int mi = 0; mi < 4; mi++)
#pragma unroll
        for (int ni = 0; ni < 4; ni++)
#pragma unroll
            for (int r = 0; r < 4; r++) acc[mi][ni][r] = 0.f;

    gemm_issue(smb, 0, A, B, K, ldb, n0, row0, 0, tid);
    gemm_issue(smb, 1, A, B, K, ldb, n0, row0, 1, tid);

    for (int kt = 0; kt < KT; kt++) {
        if (kt + 1 < KT) asm volatile("cp.async.wait_group 1;" ::: "memory");
        else             asm volatile("cp.async.wait_group 0;" ::: "memory");
        __syncthreads();
        if (kt + 2 < KT) gemm_issue(smb, (kt + 2) % 3, A, B, K, ldb, n0, row0, kt + 2, tid);

        uint32_t* st = sm + (kt % 3) * GSTAGE;
        uint32_t (*As)[36]  = (uint32_t(*)[36])st;
        uint32_t (*Bs)[132] = (uint32_t(*)[132])(st + 4608);
#pragma unroll
        for (int kk0 = 0; kk0 < 32; kk0 += 8) {
            uint32_t a[4][4], b[4][2];
#pragma unroll
            for (int mi = 0; mi < 4; mi++) {
                int rb = m0 + mi * 16 + g;
                a[mi][0] = As[rb][kk0 + t];
                a[mi][1] = As[rb + 8][kk0 + t];
                a[mi][2] = As[rb][kk0 + t + 4];
                a[mi][3] = As[rb + 8][kk0 + t + 4];
            }
#pragma unroll
            for (int ni = 0; ni < 4; ni++) {
                b[ni][0] = Bs[kk0 + t][nw + ni * 8 + g];
                b[ni][1] = Bs[kk0 + t + 4][nw + ni * 8 + g];
            }
#pragma unroll
            for (int mi = 0; mi < 4; mi++)
#pragma unroll
                for (int ni = 0; ni < 4; ni++)
                    mma8(acc[mi][ni], a[mi], b[ni]);
        }
        // no trailing sync: next iter's top sync orders compute vs. slot reuse
    }
}

// ---------------------------------------------------------------------------
// QKV projection with fused RoPE + permuted head-major stores.
// grid (12, 32): bx 0..7 -> Q, 8..9 -> K, 10..11 -> V.
// ---------------------------------------------------------------------------
__global__ __launch_bounds__(256, 2) void qkv_gemm(
    const float* __restrict__ cs, const float* __restrict__ sn)
{
    extern __shared__ uint32_t sm[];
    uint32_t smb = (uint32_t)__cvta_generic_to_shared(sm);
    const int bx = blockIdx.x, row0 = blockIdx.y * 128;
    const int tid = threadIdx.x, lane = tid & 31, wid = tid >> 5;
    const int g = lane >> 2, t = lane & 3;
    const int m0 = (wid >> 2) * 64, nw = (wid & 3) * 32;
    float acc[4][4][4];

    if (bx < 8) {
        gemm_main(sm, smb, g_xr, g_wqr, DM, bx * 128, row0, acc);
        // RoPE + store Q: head-major, d-permuted, *0.125, tf32
#pragma unroll
        for (int mi = 0; mi < 4; mi++)
#pragma unroll
            for (int ni = 0; ni < 4; ni++) {
                int gc = bx * 128 + nw + ni * 8 + 2 * t;       // even original col
                int head = gc >> 6, j = (gc & 63) >> 1;
                int pj = perm8p(j), pj2 = perm8p(j + 32);
#pragma unroll
                for (int rr = 0; rr < 2; rr++) {
                    int row = row0 + m0 + mi * 16 + g + rr * 8;
                    int n = row & (SEQ - 1), bi = row >> 11;
                    float cv = cs[n * 32 + j], sv = sn[n * 32 + j];
                    float a0 = acc[mi][ni][rr * 2], a1 = acc[mi][ni][rr * 2 + 1];
                    size_t bp = ((size_t)(bi * NH + head) * SEQ + n) * HD;
                    g_q[bp + pj]  = r2f(f2tf((a0 * cv - a1 * sv) * 0.125f));
                    g_q[bp + pj2] = r2f(f2tf((a0 * sv + a1 * cv) * 0.125f));
                }
            }
    } else if (bx < 10) {
        gemm_main(sm, smb, g_xr, g_wkr, 256, (bx - 8) * 128, row0, acc);
        // RoPE + store K: head-major, d-permuted, tf32
#pragma unroll
        for (int mi = 0; mi < 4; mi++)
#pragma unroll
            for (int ni = 0; ni < 4; ni++) {
                int gc = (bx - 8) * 128 + nw + ni * 8 + 2 * t;
                int kvh = gc >> 6, j = (gc & 63) >> 1;
                int pj = perm8p(j), pj2 = perm8p(j + 32);
#pragma unroll
                for (int rr = 0; rr < 2; rr++) {
                    int row = row0 + m0 + mi * 16 + g + rr * 8;
                    int n = row & (SEQ - 1), bi = row >> 11;
                    float cv = cs[n * 32 + j], sv = sn[n * 32 + j];
                    float a0 = acc[mi][ni][rr * 2], a1 = acc[mi][ni][rr * 2 + 1];
                    size_t bp = ((size_t)(bi * NKV + kvh) * SEQ + n) * HD;
                    g_k[bp + pj]  = r2f(f2tf(a0 * cv - a1 * sv));
                    g_k[bp + pj2] = r2f(f2tf(a0 * sv + a1 * cv));
                }
            }
    } else {
        gemm_main(sm, smb, g_xr, g_wvr, 256, (bx - 10) * 128, row0, acc);
        // Store V: head-major, within-8 row-permuted, tf32
#pragma unroll
        for (int mi = 0; mi < 4; mi++)
#pragma unroll
            for (int ni = 0; ni < 4; ni++) {
                int gc = (bx - 10) * 128 + nw + ni * 8 + 2 * t;
                int kvh = gc >> 6, d = gc & 63;
#pragma unroll
                for (int rr = 0; rr < 2; rr++) {
                    int row = row0 + m0 + mi * 16 + g + rr * 8;
                    int n = row & (SEQ - 1), bi = row >> 11;
                    int np = (n & ~7) + ((n & 7) >> 1) + ((n & 1) << 2);
                    size_t bp = ((size_t)(bi * NKV + kvh) * SEQ + np) * HD + d;
                    float2 w = make_float2(r2f(f2tf(acc[mi][ni][rr * 2])),
                                           r2f(f2tf(acc[mi][ni][rr * 2 + 1])));
                    *(float2*)&g_v[bp] = w;
                }
            }
    }
}

// ---------------------------------------------------------------------------
// Output projection (plain epilogue, reads pre-rounded g_attn + g_wor raw)
// ---------------------------------------------------------------------------
__global__ __launch_bounds__(256, 2) void out_gemm(float* __restrict__ out)
{
    extern __shared__ uint32_t sm[];
    uint32_t smb = (uint32_t)__cvta_generic_to_shared(sm);
    const int tid = threadIdx.x, lane = tid & 31, wid = tid >> 5;
    const int g = lane >> 2, t = lane & 3;
    const int m0 = (wid >> 2) * 64, nw = (wid & 3) * 32;
    const int n0 = blockIdx.x * 128, row0 = blockIdx.y * 128;
    float acc[4][4][4];
    gemm_main(sm, smb, g_attn, g_wor, DM, n0, row0, acc);
#pragma unroll
    for (int mi = 0; mi < 4; mi++) {
        int r = row0 + m0 + mi * 16 + g;
#pragma unroll
        for (int ni = 0; ni < 4; ni++) {
            int c = n0 + nw + ni * 8 + 2 * t;
            *(float2*)(out + (size_t)r * DM + c)       = make_float2(acc[mi][ni][0], acc[mi][ni][1]);
            *(float2*)(out + (size_t)(r + 8) * DM + c) = make_float2(acc[mi][ni][2], acc[mi][ni][3]);
        }
    }
}

// ---------------------------------------------------------------------------
// Flash attention: Q resident, 2-stage cp.async double-buffered K/V.
// Smem (u32 words): Qs[128*72]=9216 | stage s: Ks[64*72] + Vs[64*72] = 9216.
// Total 27648 words = 110592 B -> 2 CTAs/SM.
// ---------------------------------------------------------------------------
#define ATT_SMEM 110592

__device__ __forceinline__ void attn_issue_kv(uint32_t smb, int slot,
    const float* __restrict__ Kb, const float* __restrict__ Vb, int kt, int tid)
{
    uint32_t base = smb + (9216 + slot * 9216) * 4;
    const float* K0 = Kb + (size_t)kt * 64 * HD;
    const float* V0 = Vb + (size_t)kt * 64 * HD;
#pragma unroll
    for (int i = 0; i < 4; i++) {
        int c = tid + i * 256;
        int r = c >> 4, col = (c & 15) << 2;
        cpa16(base + (r * 72 + col) * 4, K0 + r * HD + col);
    }
#pragma unroll
    for (int i = 0; i < 4; i++) {
        int c = tid + i * 256;
        int r = c >> 4, col = (c & 15) << 2;
        cpa16(base + (4608 + r * 72 + col) * 4, V0 + r * HD + col);
    }
    CPA_COMMIT();
}

__global__ __launch_bounds__(256, 2) void attn_mma()
{
    extern __shared__ uint32_t sm[];
    uint32_t smb = (uint32_t)__cvta_generic_to_shared(sm);
    const int b = blockIdx.z, h = blockIdx.y;
    const int n0 = blockIdx.x * 128;
    const int kvh = h >> 2;
    const int tid = threadIdx.x, lane = tid & 31, wid = tid >> 5;
    const int g = lane >> 2, t = lane & 3;
    const int m0 = wid * 16;

    const float* Qb = g_q + ((size_t)(b * NH + h) * SEQ + n0) * HD;
    const float* Kb = g_k + ((size_t)(b * NKV + kvh) * SEQ) * HD;
    const float* Vb = g_v + ((size_t)(b * NKV + kvh) * SEQ) * HD;

    // Q tile (group 0): 128 rows x 64 words -> stride-72 rows
#pragma unroll
    for (int i = 0; i < 8; i++) {
        int c = tid + i * 256;
        int r = c >> 4, col = (c & 15) << 2;
        cpa16(smb + (r * 72 + col) * 4, Qb + r * HD + col);
    }
    CPA_COMMIT();
    attn_issue_kv(smb, 0, Kb, Vb, 0, tid);

    uint32_t* Qs = sm;
    float m0s = -1e30f, m1s = -1e30f, l0s = 0.f, l1s = 0.f;
    float o[8][4];
#pragma unroll
    for (int ni = 0; ni < 8; ni++)
#pragma unroll
        for (int r = 0; r < 4; r++) o[ni][r] = 0.f;

    const int KT = SEQ / 64;
    for (int kt = 0; kt < KT; kt++) {
        if (kt + 1 < KT) {
            attn_issue_kv(smb, (kt + 1) & 1, Kb, Vb, kt + 1, tid);
            asm volatile("cp.async.wait_group 1;" ::: "memory");
        } else {
            asm volatile("cp.async.wait_group 0;" ::: "memory");
        }
        __syncthreads();
        uint32_t* Ks = sm + 9216 + (kt & 1) * 9216;
        uint32_t* Vs = Ks + 4608;

        // S = Q * K^T
        float s[8][4];
#pragma unroll
        for (int ni = 0; ni < 8; ni++)
#pragma unroll
            for (int r = 0; r < 4; r++) s[ni][r] = 0.f;
#pragma unroll
        for (int kk = 0; kk < 8; kk++) {
            uint32_t a[4];
            uint2 p0 = *(const uint2*)&Qs[(m0 + g) * 72 + kk * 8 + 2 * t];
            uint2 p1 = *(const uint2*)&Qs[(m0 + g + 8) * 72 + kk * 8 + 2 * t];
            a[0] = p0.x; a[1] = p1.x; a[2] = p0.y; a[3] = p1.y;
#pragma unroll
            for (int ni = 0; ni < 8; ni++) {
                uint2 bv = *(const uint2*)&Ks[(ni * 8 + g) * 72 + kk * 8 + 2 * t];
                uint32_t bb[2] = {bv.x, bv.y};
                mma8(s[ni], a, bb);
            }
        }

        // online softmax (rows m0+g and m0+g+8; cols spread over t, xor 1,2)
        float mx0 = -1e30f, mx1 = -1e30f;
#pragma unroll
        for (int ni = 0; ni < 8; ni++) {
            mx0 = fmaxf(mx0, fmaxf(s[ni][0], s[ni][1]));
            mx1 = fmaxf(mx1, fmaxf(s[ni][2], s[ni][3]));
        }
        mx0 = fmaxf(mx0, __shfl_xor_sync(0xffffffffu, mx0, 1));
        mx0 = fmaxf(mx0, __shfl_xor_sync(0xffffffffu, mx0, 2));
        mx1 = fmaxf(mx1, __shfl_xor_sync(0xffffffffu, mx1, 1));
        mx1 = fmaxf(mx1, __shfl_xor_sync(0xffffffffu, mx1, 2));

        float mn0 = fmaxf(m0s, mx0), mn1 = fmaxf(m1s, mx1);
        float cor0 = __expf(m0s - mn0), cor1 = __expf(m1s - mn1);
        m0s = mn0; m1s = mn1;

        float rs0 = 0.f, rs1 = 0.f;
        uint32_t pf[8][4];
#pragma unroll
        for (int ni = 0; ni < 8; ni++) {
            float e0 = __expf(s[ni][0] - mn0);
            float e1 = __expf(s[ni][1] - mn0);
            float e2 = __expf(s[ni][2] - mn1);
            float e3 = __expf(s[ni][3] - mn1);
            rs0 += e0 + e1; rs1 += e2 + e3;
            pf[ni][0] = f2tf(e0); pf[ni][1] = f2tf(e2);
            pf[ni][2] = f2tf(e1); pf[ni][3] = f2tf(e3);
        }
        rs0 += __shfl_xor_sync(0xffffffffu, rs0, 1);
        rs0 += __shfl_xor_sync(0xffffffffu, rs0, 2);
        rs1 += __shfl_xor_sync(0xffffffffu, rs1, 1);
        rs1 += __shfl_xor_sync(0xffffffffu, rs1, 2);
        l0s = l0s * cor0 + rs0;
        l1s = l1s * cor1 + rs1;

#pragma unroll
        for (int ni = 0; ni < 8; ni++) {
            o[ni][0] *= cor0; o[ni][1] *= cor0;
            o[ni][2] *= cor1; o[ni][3] *= cor1;
        }

        // O += P * V (P from registers; Vs rows pre-permuted)
#pragma unroll
        for (int kk = 0; kk < 8; kk++) {
#pragma unroll
            for (int ni = 0; ni < 8; ni++) {
                uint32_t bb[2];
                bb[0] = Vs[(kk * 8 + t) * 72 + ni * 8 + g];
                bb[1] = Vs[(kk * 8 + t + 4) * 72 + ni * 8 + g];
                mma8(o[ni], pf[kk], bb);
            }
        }
        __syncthreads();   // stage consumed; safe for overwrite next iter
    }

    // epilogue: normalize, round to tf32, write (b,n,1024) for out_gemm
    float inv0 = 1.f / l0s, inv1 = 1.f / l1s;
    size_t r0 = (size_t)b * SEQ + n0 + m0 + g;
#pragma unroll
    for (int ni = 0; ni < 8; ni++) {
        int col = h * HD + ni * 8 + 2 * t;
        *(float2*)&g_attn[r0 * DM + col] =
            make_float2(r2f(f2tf(o[ni][0] * inv0)), r2f(f2tf(o[ni][1] * inv0)));
        *(float2*)&g_attn[(r0 + 8) * DM + col] =
            make_float2(r2f(f2tf(o[ni][2] * inv1)), r2f(f2tf(o[ni][3] * inv1)));
    }
}

// ---------------------------------------------------------------------------
extern "C" void kernel_launch(void* const* d_in, const int* in_sizes, int n_in,
                              void* d_out, int out_size)
{
    const float* x  = (const float*)d_in[0];
    const float* cs = (const float*)d_in[1];
    const float* sn = (const float*)d_in[2];
    const float* Wq = (const float*)d_in[3];
    const float* Wk = (const float*)d_in[4];
    const float* Wv = (const float*)d_in[5];
    const float* Wo = (const float*)d_in[6];
    float* out = (float*)d_out;
    (void)in_sizes; (void)n_in; (void)out_size;

    cudaFuncSetAttribute(qkv_gemm, cudaFuncAttributeMaxDynamicSharedMemorySize, GEMM_SMEM);
    cudaFuncSetAttribute(out_gemm, cudaFuncAttributeMaxDynamicSharedMemorySize, GEMM_SMEM);
    cudaFuncSetAttribute(attn_mma, cudaFuncAttributeMaxDynamicSharedMemorySize, ATT_SMEM);

    // 1) round x + weights onto the tf32 grid (1703936 float4 / 256)
    prep_round<<<6656, 256>>>(x, Wq, Wk, Wv, Wo);

    // 2) QKV projections + fused RoPE + permuted head-major stores
    qkv_gemm<<<dim3(12, 32), 256, GEMM_SMEM>>>(cs, sn);

    // 3) attention
    attn_mma<<<dim3(SEQ / 128, NH, BB), 256, ATT_SMEM>>>();

    // 4) output projection
    out_gemm<<<dim3(8, 32), 256, GEMM_SMEM>>>(out);
}

// round 5
// speedup vs baseline: 3.9930x; 1.0317x over previous
#include <cuda_runtime.h>
#include <cstdint>

#define NH   16
#define NKV  4
#define HD   64
#define DM   1024
#define BB   2
#define SEQ  2048
#define MROWS (BB*SEQ)   // 4096

// ---------------------------------------------------------------------------
// Scratch (allocation-free device globals)
// ---------------------------------------------------------------------------
__device__ float g_xr [(size_t)MROWS * DM];       // tf32-rounded x
__device__ float g_wqr[(size_t)DM * DM];
__device__ float g_wkr[(size_t)DM * 256];
__device__ float g_wvr[(size_t)DM * 256];
__device__ float g_wor[(size_t)DM * DM];
__device__ float g_q  [(size_t)BB * NH  * SEQ * HD];  // head-major, d-permuted, *0.125, rope'd
__device__ float g_k  [(size_t)BB * NKV * SEQ * HD];  // head-major, d-permuted, rope'd
__device__ float g_v  [(size_t)BB * NKV * HD * SEQ];  // head-major TRANSPOSED: [d][seq]
__device__ float g_attn[(size_t)MROWS * DM];          // (b,n,1024), tf32-rounded

// ---------------------------------------------------------------------------
// helpers
// ---------------------------------------------------------------------------
__device__ __forceinline__ uint32_t f2tf(float f) {
    uint32_t u;
    asm("cvt.rna.tf32.f32 %0, %1;" : "=r"(u) : "f"(f));
    return u;
}
__device__ __forceinline__ float r2f(uint32_t u) { return __uint_as_float(u); }

// position of head-col j under the within-8-group d-permute (for Q/K S-gemm)
__device__ __forceinline__ int perm8p(int j) {
    int u = j & 7;
    return (j & ~7) + ((u < 4) ? 2 * u : 2 * (u - 4) + 1);
}

__device__ __forceinline__ void mma8(float c[4], const uint32_t a[4], const uint32_t b[2]) {
    asm volatile(
        "mma.sync.aligned.m16n8k8.row.col.f32.tf32.tf32.f32 "
        "{%0,%1,%2,%3},{%4,%5,%6,%7},{%8,%9},{%0,%1,%2,%3};"
        : "+f"(c[0]), "+f"(c[1]), "+f"(c[2]), "+f"(c[3])
        : "r"(a[0]), "r"(a[1]), "r"(a[2]), "r"(a[3]), "r"(b[0]), "r"(b[1]));
}

__device__ __forceinline__ void cpa16(uint32_t dst, const void* src) {
    asm volatile("cp.async.cg.shared.global [%0], [%1], 16;" :: "r"(dst), "l"(src) : "memory");
}
#define CPA_COMMIT() asm volatile("cp.async.commit_group;" ::: "memory")

// ---------------------------------------------------------------------------
// Pre-pass: round x + weights to the tf32 grid (then mma can eat them raw).
// ---------------------------------------------------------------------------
__global__ void prep_round(const float* __restrict__ x,  const float* __restrict__ Wq,
                           const float* __restrict__ Wk, const float* __restrict__ Wv,
                           const float* __restrict__ Wo)
{
    size_t i = (size_t)blockIdx.x * 256 + threadIdx.x;   // float4 index
    const float* src; float* dst; size_t off;
    if      (i < 1048576) { src = x;  dst = g_xr;  off = i; }
    else if (i < 1310720) { src = Wq; dst = g_wqr; off = i - 1048576; }
    else if (i < 1376256) { src = Wk; dst = g_wkr; off = i - 1310720; }
    else if (i < 1441792) { src = Wv; dst = g_wvr; off = i - 1376256; }
    else                  { src = Wo; dst = g_wor; off = i - 1441792; }
    float4 v = ((const float4*)src)[off];
    v.x = r2f(f2tf(v.x)); v.y = r2f(f2tf(v.y));
    v.z = r2f(f2tf(v.z)); v.w = r2f(f2tf(v.w));
    ((float4*)dst)[off] = v;
}

// ---------------------------------------------------------------------------
// cp.async 3-stage GEMM: 128x128 tile, kstep 32, 256 threads, warp tile 64x32.
// Stage: As[128][40] (5120 w) + Bs[32][132] (4224 w) = 9344 words.
// Frag reads use logical-k pairing (t<->2t, t+4<->2t+1):
//   A pair = LDS.64, bank (8g+2t)%32 conflict-free (ld=40).
//   B rows 2t/2t+1, bank (8t+g)%32 conflict-free (ld=132).
// ---------------------------------------------------------------------------
#define GSTAGE 9344
#define GEMM_SMEM (3 * GSTAGE * 4)   // 112128 B

__device__ __forceinline__ void gemm_issue(uint32_t smb, int slot,
    const float* __restrict__ A, const float* __restrict__ B,
    int K, int ldb, int n0, int row0, int kt, int tid)
{
    uint32_t base = smb + slot * (GSTAGE * 4);
#pragma unroll
    for (int i = 0; i < 4; i++) {
        int c = tid + i * 256;
        int r = c >> 3, col = (c & 7) << 2;
        cpa16(base + (r * 40 + col) * 4, A + (size_t)(row0 + r) * K + kt * 32 + col);
    }
#pragma unroll
    for (int i = 0; i < 4; i++) {
        int c = tid + i * 256;
        int kk = c >> 5, nn = (c & 31) << 2;
        cpa16(base + (5120 + kk * 132 + nn) * 4, B + (size_t)(kt * 32 + kk) * ldb + n0 + nn);
    }
    CPA_COMMIT();
}

__device__ __forceinline__ void gemm_main(uint32_t* sm, uint32_t smb,
    const float* __restrict__ A, const float* __restrict__ B,
    int ldb, int n0, int row0, float acc[4][4][4])
{
    const int K = DM, KT = DM / 32;
    const int tid = threadIdx.x, lane = tid & 31, wid = tid >> 5;
    const int g = lane >> 2, t = lane & 3;
    const int m0 = (wid >> 2) * 64, nw = (wid & 3) * 32;

#pragma unroll
    for (int mi = 0; mi < 4; mi++)
#pragma unroll
        for (int ni = 0; ni < 4; ni++)
#pragma unroll
            for (int r = 0; r < 4; r++) acc[mi][ni][r] = 0.f;

    gemm_issue(smb, 0, A, B, K, ldb, n0, row0, 0, tid);
    gemm_issue(smb, 1, A, B, K, ldb, n0, row0, 1, tid);

    for (int kt = 0; kt < KT; kt++) {
        if (kt + 1 < KT) asm volatile("cp.async.wait_group 1;" ::: "memory");
        else             asm volatile("cp.async.wait_group 0;" ::: "memory");
        __syncthreads();
        if (kt + 2 < KT) gemm_issue(smb, (kt + 2) % 3, A, B, K, ldb, n0, row0, kt + 2, tid);

        uint32_t* st = sm + (kt % 3) * GSTAGE;
        uint32_t (*As)[40]  = (uint32_t(*)[40])st;
        uint32_t (*Bs)[132] = (uint32_t(*)[132])(st + 5120);
#pragma unroll
        for (int kk0 = 0; kk0 < 32; kk0 += 8) {
            uint32_t a[4][4], b[4][2];
#pragma unroll
            for (int mi = 0; mi < 4; mi++) {
                int rb = m0 + mi * 16 + g;
                uint2 av0 = *(const uint2*)&As[rb][kk0 + 2 * t];       // phys 2t, 2t+1
                uint2 av1 = *(const uint2*)&As[rb + 8][kk0 + 2 * t];
                a[mi][0] = av0.x; a[mi][1] = av1.x; a[mi][2] = av0.y; a[mi][3] = av1.y;
            }
#pragma unroll
            for (int ni = 0; ni < 4; ni++) {
                b[ni][0] = Bs[kk0 + 2 * t][nw + ni * 8 + g];           // phys 2t
                b[ni][1] = Bs[kk0 + 2 * t + 1][nw + ni * 8 + g];       // phys 2t+1
            }
#pragma unroll
            for (int mi = 0; mi < 4; mi++)
#pragma unroll
                for (int ni = 0; ni < 4; ni++)
                    mma8(acc[mi][ni], a[mi], b[ni]);
        }
    }
}

// ---------------------------------------------------------------------------
// QKV projection + fused RoPE + permuted head-major stores (V transposed).
// grid (12, 32): bx 0..7 -> Q, 8..9 -> K, 10..11 -> V.
// ---------------------------------------------------------------------------
__global__ __launch_bounds__(256, 2) void qkv_gemm(
    const float* __restrict__ cs, const float* __restrict__ sn)
{
    extern __shared__ uint32_t sm[];
    uint32_t smb = (uint32_t)__cvta_generic_to_shared(sm);
    const int bx = blockIdx.x, row0 = blockIdx.y * 128;
    const int tid = threadIdx.x, lane = tid & 31, wid = tid >> 5;
    const int g = lane >> 2, t = lane & 3;
    const int m0 = (wid >> 2) * 64, nw = (wid & 3) * 32;
    float acc[4][4][4];

    if (bx < 8) {
        gemm_main(sm, smb, g_xr, g_wqr, DM, bx * 128, row0, acc);
#pragma unroll
        for (int mi = 0; mi < 4; mi++)
#pragma unroll
            for (int ni = 0; ni < 4; ni++) {
                int gc = bx * 128 + nw + ni * 8 + 2 * t;       // even original col
                int head = gc >> 6, j = (gc & 63) >> 1;
                int pj = perm8p(j), pj2 = perm8p(j + 32);
#pragma unroll
                for (int rr = 0; rr < 2; rr++) {
                    int row = row0 + m0 + mi * 16 + g + rr * 8;
                    int n = row & (SEQ - 1), bi = row >> 11;
                    float cv = cs[n * 32 + j], sv = sn[n * 32 + j];
                    float a0 = acc[mi][ni][rr * 2], a1 = acc[mi][ni][rr * 2 + 1];
                    size_t bp = ((size_t)(bi * NH + head) * SEQ + n) * HD;
                    g_q[bp + pj]  = r2f(f2tf((a0 * cv - a1 * sv) * 0.125f));
                    g_q[bp + pj2] = r2f(f2tf((a0 * sv + a1 * cv) * 0.125f));
                }
            }
    } else if (bx < 10) {
        gemm_main(sm, smb, g_xr, g_wkr, 256, (bx - 8) * 128, row0, acc);
#pragma unroll
        for (int mi = 0; mi < 4; mi++)
#pragma unroll
            for (int ni = 0; ni < 4; ni++) {
                int gc = (bx - 8) * 128 + nw + ni * 8 + 2 * t;
                int kvh = gc >> 6, j = (gc & 63) >> 1;
                int pj = perm8p(j), pj2 = perm8p(j + 32);
#pragma unroll
                for (int rr = 0; rr < 2; rr++) {
                    int row = row0 + m0 + mi * 16 + g + rr * 8;
                    int n = row & (SEQ - 1), bi = row >> 11;
                    float cv = cs[n * 32 + j], sv = sn[n * 32 + j];
                    float a0 = acc[mi][ni][rr * 2], a1 = acc[mi][ni][rr * 2 + 1];
                    size_t bp = ((size_t)(bi * NKV + kvh) * SEQ + n) * HD;
                    g_k[bp + pj]  = r2f(f2tf(a0 * cv - a1 * sv));
                    g_k[bp + pj2] = r2f(f2tf(a0 * sv + a1 * cv));
                }
            }
    } else {
        gemm_main(sm, smb, g_xr, g_wvr, 256, (bx - 10) * 128, row0, acc);
        // V: transposed store g_v[bh][d][n]
#pragma unroll
        for (int mi = 0; mi < 4; mi++)
#pragma unroll
            for (int ni = 0; ni < 4; ni++) {
                int gc = (bx - 10) * 128 + nw + ni * 8 + 2 * t;
                int kvh = gc >> 6, d = gc & 63;
                size_t hb = (size_t)0;
#pragma unroll
                for (int rr = 0; rr < 2; rr++) {
                    int row = row0 + m0 + mi * 16 + g + rr * 8;
                    int n = row & (SEQ - 1), bi = row >> 11;
                    hb = ((size_t)(bi * NKV + kvh) * HD);
                    g_v[(hb + d) * SEQ + n]     = r2f(f2tf(acc[mi][ni][rr * 2]));
                    g_v[(hb + d + 1) * SEQ + n] = r2f(f2tf(acc[mi][ni][rr * 2 + 1]));
                }
            }
    }
}

// ---------------------------------------------------------------------------
// Output projection
// ---------------------------------------------------------------------------
__global__ __launch_bounds__(256, 2) void out_gemm(float* __restrict__ out)
{
    extern __shared__ uint32_t sm[];
    uint32_t smb = (uint32_t)__cvta_generic_to_shared(sm);
    const int tid = threadIdx.x, lane = tid & 31, wid = tid >> 5;
    const int g = lane >> 2, t = lane & 3;
    const int m0 = (wid >> 2) * 64, nw = (wid & 3) * 32;
    const int n0 = blockIdx.x * 128, row0 = blockIdx.y * 128;
    float acc[4][4][4];
    gemm_main(sm, smb, g_attn, g_wor, DM, n0, row0, acc);
#pragma unroll
    for (int mi = 0; mi < 4; mi++) {
        int r = row0 + m0 + mi * 16 + g;
#pragma unroll
        for (int ni = 0; ni < 4; ni++) {
            int c = n0 + nw + ni * 8 + 2 * t;
            *(float2*)(out + (size_t)r * DM + c)       = make_float2(acc[mi][ni][0], acc[mi][ni][1]);
            *(float2*)(out + (size_t)(r + 8) * DM + c) = make_float2(acc[mi][ni][2], acc[mi][ni][3]);
        }
    }
}

// ---------------------------------------------------------------------------
// Flash attention: Q resident, 2-stage cp.async K/V; V transposed (d x keys).
// Smem (u32): Qs[128*72]=9216 | per stage Ks[64*72] + Vt[64*72] = 9216.
// Total 27648 words = 110592 B -> 2 CTAs/SM.
// PV b-frags are LDS.64 (keys 2t,2t+1 adjacent in Vt rows).
// ---------------------------------------------------------------------------
#define ATT_SMEM 110592

__device__ __forceinline__ void attn_issue_kv(uint32_t smb, int slot,
    const float* __restrict__ Kb, const float* __restrict__ Vb, int kt, int tid)
{
    uint32_t base = smb + (9216 + slot * 9216) * 4;
    const float* K0 = Kb + (size_t)kt * 64 * HD;
#pragma unroll
    for (int i = 0; i < 4; i++) {
        int c = tid + i * 256;
        int r = c >> 4, col = (c & 15) << 2;
        cpa16(base + (r * 72 + col) * 4, K0 + r * HD + col);
    }
    // V^T tile: 64 d-rows x 64 keys (keys kt*64 .. +63 contiguous per d-row)
#pragma unroll
    for (int i = 0; i < 4; i++) {
        int c = tid + i * 256;
        int r = c >> 4, col = (c & 15) << 2;
        cpa16(base + (4608 + r * 72 + col) * 4, Vb + (size_t)r * SEQ + kt * 64 + col);
    }
    CPA_COMMIT();
}

__global__ __launch_bounds__(256, 2) void attn_mma()
{
    extern __shared__ uint32_t sm[];
    uint32_t smb = (uint32_t)__cvta_generic_to_shared(sm);
    const int b = blockIdx.z, h = blockIdx.y;
    const int n0 = blockIdx.x * 128;
    const int kvh = h >> 2;
    const int tid = threadIdx.x, lane = tid & 31, wid = tid >> 5;
    const int g = lane >> 2, t = lane & 3;
    const int m0 = wid * 16;

    const float* Qb = g_q + ((size_t)(b * NH + h) * SEQ + n0) * HD;
    const float* Kb = g_k + ((size_t)(b * NKV + kvh) * SEQ) * HD;
    const float* Vb = g_v + ((size_t)(b * NKV + kvh) * HD) * SEQ;

#pragma unroll
    for (int i = 0; i < 8; i++) {
        int c = tid + i * 256;
        int r = c >> 4, col = (c & 15) << 2;
        cpa16(smb + (r * 72 + col) * 4, Qb + r * HD + col);
    }
    CPA_COMMIT();
    attn_issue_kv(smb, 0, Kb, Vb, 0, tid);

    uint32_t* Qs = sm;
    float m0s = -1e30f, m1s = -1e30f, l0s = 0.f, l1s = 0.f;
    float o[8][4];
#pragma unroll
    for (int ni = 0; ni < 8; ni++)
#pragma unroll
        for (int r = 0; r < 4; r++) o[ni][r] = 0.f;

    const int KT = SEQ / 64;
    for (int kt = 0; kt < KT; kt++) {
        if (kt + 1 < KT) {
            attn_issue_kv(smb, (kt + 1) & 1, Kb, Vb, kt + 1, tid);
            asm volatile("cp.async.wait_group 1;" ::: "memory");
        } else {
            asm volatile("cp.async.wait_group 0;" ::: "memory");
        }
        __syncthreads();
        uint32_t* Ks = sm + 9216 + (kt & 1) * 9216;
        uint32_t* Vt = Ks + 4608;

        // S = Q * K^T
        float s[8][4];
#pragma unroll
        for (int ni = 0; ni < 8; ni++)
#pragma unroll
            for (int r = 0; r < 4; r++) s[ni][r] = 0.f;
#pragma unroll
        for (int kk = 0; kk < 8; kk++) {
            uint32_t a[4];
            uint2 p0 = *(const uint2*)&Qs[(m0 + g) * 72 + kk * 8 + 2 * t];
            uint2 p1 = *(const uint2*)&Qs[(m0 + g + 8) * 72 + kk * 8 + 2 * t];
            a[0] = p0.x; a[1] = p1.x; a[2] = p0.y; a[3] = p1.y;
#pragma unroll
            for (int ni = 0; ni < 8; ni++) {
                uint2 bv = *(const uint2*)&Ks[(ni * 8 + g) * 72 + kk * 8 + 2 * t];
                uint32_t bb[2] = {bv.x, bv.y};
                mma8(s[ni], a, bb);
            }
        }

        // online softmax; thread owns keys 2t,2t+1 per row m0+g / m0+g+8
        float mx0 = -1e30f, mx1 = -1e30f;
#pragma unroll
        for (int ni = 0; ni < 8; ni++) {
            mx0 = fmaxf(mx0, fmaxf(s[ni][0], s[ni][1]));
            mx1 = fmaxf(mx1, fmaxf(s[ni][2], s[ni][3]));
        }
        mx0 = fmaxf(mx0, __shfl_xor_sync(0xffffffffu, mx0, 1));
        mx0 = fmaxf(mx0, __shfl_xor_sync(0xffffffffu, mx0, 2));
        mx1 = fmaxf(mx1, __shfl_xor_sync(0xffffffffu, mx1, 1));
        mx1 = fmaxf(mx1, __shfl_xor_sync(0xffffffffu, mx1, 2));

        float mn0 = fmaxf(m0s, mx0), mn1 = fmaxf(m1s, mx1);
        float cor0 = __expf(m0s - mn0), cor1 = __expf(m1s - mn1);
        m0s = mn0; m1s = mn1;

        float rs0 = 0.f, rs1 = 0.f;
#pragma unroll
        for (int ni = 0; ni < 8; ni++) {
            s[ni][0] = __expf(s[ni][0] - mn0);
            s[ni][1] = __expf(s[ni][1] - mn0);
            s[ni][2] = __expf(s[ni][2] - mn1);
            s[ni][3] = __expf(s[ni][3] - mn1);
            rs0 += s[ni][0] + s[ni][1];
            rs1 += s[ni][2] + s[ni][3];
        }
        rs0 += __shfl_xor_sync(0xffffffffu, rs0, 1);
        rs0 += __shfl_xor_sync(0xffffffffu, rs0, 2);
        rs1 += __shfl_xor_sync(0xffffffffu, rs1, 1);
        rs1 += __shfl_xor_sync(0xffffffffu, rs1, 2);
        l0s = l0s * cor0 + rs0;
        l1s = l1s * cor1 + rs1;

#pragma unroll
        for (int ni = 0; ni < 8; ni++) {
            o[ni][0] *= cor0; o[ni][1] *= cor0;
            o[ni][2] *= cor1; o[ni][3] *= cor1;
        }

        // O += P * V : A-frag on the fly (keys 2t<->slot k=t, 2t+1<->k=t+4),
        // B-frag single LDS.64 from Vt row (d), cols 2t,2t+1.
#pragma unroll
        for (int kk = 0; kk < 8; kk++) {
            uint32_t a[4];
            a[0] = f2tf(s[kk][0]);   // key 2t,  row g
            a[1] = f2tf(s[kk][2]);   // key 2t,  row g+8
            a[2] = f2tf(s[kk][1]);   // key 2t+1, row g
            a[3] = f2tf(s[kk][3]);   // key 2t+1, row g+8
#pragma unroll
            for (int ni = 0; ni < 8; ni++) {
                uint2 bv = *(const uint2*)&Vt[(ni * 8 + g) * 72 + kk * 8 + 2 * t];
                uint32_t bb[2] = {bv.x, bv.y};
                mma8(o[ni], a, bb);
            }
        }
        __syncthreads();   // stage consumed; safe to overwrite next iter
    }

    // epilogue: normalize, round to tf32, write (b,n,1024) for out_gemm
    float inv0 = 1.f / l0s, inv1 = 1.f / l1s;
    size_t r0 = (size_t)b * SEQ + n0 + m0 + g;
#pragma unroll
    for (int ni = 0; ni < 8; ni++) {
        int col = h * HD + ni * 8 + 2 * t;
        *(float2*)&g_attn[r0 * DM + col] =
            make_float2(r2f(f2tf(o[ni][0] * inv0)), r2f(f2tf(o[ni][1] * inv0)));
        *(float2*)&g_attn[(r0 + 8) * DM + col] =
            make_float2(r2f(f2tf(o[ni][2] * inv1)), r2f(f2tf(o[ni][3] * inv1)));
    }
}

// ---------------------------------------------------------------------------
extern "C" void kernel_launch(void* const* d_in, const int* in_sizes, int n_in,
                              void* d_out, int out_size)
{
    const float* x  = (const float*)d_in[0];
    const float* cs = (const float*)d_in[1];
    const float* sn = (const float*)d_in[2];
    const float* Wq = (const float*)d_in[3];
    const float* Wk = (const float*)d_in[4];
    const float* Wv = (const float*)d_in[5];
    const float* Wo = (const float*)d_in[6];
    float* out = (float*)d_out;
    (void)in_sizes; (void)n_in; (void)out_size;

    cudaFuncSetAttribute(qkv_gemm, cudaFuncAttributeMaxDynamicSharedMemorySize, GEMM_SMEM);
    cudaFuncSetAttribute(out_gemm, cudaFuncAttributeMaxDynamicSharedMemorySize, GEMM_SMEM);
    cudaFuncSetAttribute(attn_mma, cudaFuncAttributeMaxDynamicSharedMemorySize, ATT_SMEM);

    // 1) round x + weights onto the tf32 grid
    prep_round<<<6656, 256>>>(x, Wq, Wk, Wv, Wo);

    // 2) QKV projections + fused RoPE + permuted head-major stores
    qkv_gemm<<<dim3(12, 32), 256, GEMM_SMEM>>>(cs, sn);

    // 3) attention
    attn_mma<<<dim3(SEQ / 128, NH, BB), 256, ATT_SMEM>>>();

    // 4) output projection
    out_gemm<<<dim3(8, 32), 256, GEMM_SMEM>>>(out);
}

// round 6
// speedup vs baseline: 4.2326x; 1.0600x over previous
#include <cuda_runtime.h>
#include <cstdint>

#define NH   16
#define NKV  4
#define HD   64
#define DM   1024
#define BB   2
#define SEQ  2048
#define MROWS (BB*SEQ)   // 4096

// Q pre-scale: HD^-0.5 * log2(e)  (softmax done in exp2 domain)
#define QSC 0.18033688011112042f

// ---------------------------------------------------------------------------
// Scratch (allocation-free device globals)
// ---------------------------------------------------------------------------
__device__ float g_xr [(size_t)MROWS * DM];       // tf32-rounded x
__device__ float g_wqr[(size_t)DM * DM];
__device__ float g_wkr[(size_t)DM * 256];
__device__ float g_wvr[(size_t)DM * 256];
__device__ float g_wor[(size_t)DM * DM];
__device__ float g_q  [(size_t)BB * NH  * SEQ * HD];  // head-major, d-permuted, *QSC, rope'd
__device__ float g_k  [(size_t)BB * NKV * SEQ * HD];  // head-major, d-permuted, rope'd
__device__ float g_v  [(size_t)BB * NKV * HD * SEQ];  // head-major TRANSPOSED: [d][seq]
__device__ float g_attn[(size_t)MROWS * DM];          // (b,n,1024), tf32-rounded

// ---------------------------------------------------------------------------
// helpers
// ---------------------------------------------------------------------------
__device__ __forceinline__ uint32_t f2tf(float f) {
    uint32_t u;
    asm("cvt.rna.tf32.f32 %0, %1;" : "=r"(u) : "f"(f));
    return u;
}
__device__ __forceinline__ float r2f(uint32_t u) { return __uint_as_float(u); }

__device__ __forceinline__ float ex2f(float x) {
    float r;
    asm("ex2.approx.ftz.f32 %0, %1;" : "=f"(r) : "f"(x));
    return r;
}

// position of head-col j under the within-8-group d-permute (for Q/K S-gemm)
__device__ __forceinline__ int perm8p(int j) {
    int u = j & 7;
    return (j & ~7) + ((u < 4) ? 2 * u : 2 * (u - 4) + 1);
}

__device__ __forceinline__ void mma8(float c[4], const uint32_t a[4], const uint32_t b[2]) {
    asm volatile(
        "mma.sync.aligned.m16n8k8.row.col.f32.tf32.tf32.f32 "
        "{%0,%1,%2,%3},{%4,%5,%6,%7},{%8,%9},{%0,%1,%2,%3};"
        : "+f"(c[0]), "+f"(c[1]), "+f"(c[2]), "+f"(c[3])
        : "r"(a[0]), "r"(a[1]), "r"(a[2]), "r"(a[3]), "r"(b[0]), "r"(b[1]));
}

__device__ __forceinline__ void cpa16(uint32_t dst, const void* src) {
    asm volatile("cp.async.cg.shared.global [%0], [%1], 16;" :: "r"(dst), "l"(src) : "memory");
}
#define CPA_COMMIT() asm volatile("cp.async.commit_group;" ::: "memory")

// ---------------------------------------------------------------------------
// Pre-pass: round x + weights to the tf32 grid (then mma can eat them raw).
// ---------------------------------------------------------------------------
__global__ void prep_round(const float* __restrict__ x,  const float* __restrict__ Wq,
                           const float* __restrict__ Wk, const float* __restrict__ Wv,
                           const float* __restrict__ Wo)
{
    size_t i = (size_t)blockIdx.x * 256 + threadIdx.x;   // float4 index
    const float* src; float* dst; size_t off;
    if      (i < 1048576) { src = x;  dst = g_xr;  off = i; }
    else if (i < 1310720) { src = Wq; dst = g_wqr; off = i - 1048576; }
    else if (i < 1376256) { src = Wk; dst = g_wkr; off = i - 1310720; }
    else if (i < 1441792) { src = Wv; dst = g_wvr; off = i - 1376256; }
    else                  { src = Wo; dst = g_wor; off = i - 1441792; }
    float4 v = ((const float4*)src)[off];
    v.x = r2f(f2tf(v.x)); v.y = r2f(f2tf(v.y));
    v.z = r2f(f2tf(v.z)); v.w = r2f(f2tf(v.w));
    ((float4*)dst)[off] = v;
}

// ---------------------------------------------------------------------------
// cp.async 3-stage GEMM: 128x128 tile, kstep 32, 256 threads, warp tile 64x32.
// Stage: As[128][40] (5120 w) + Bs[32][132] (4224 w) = 9344 words.
// Frag reads use logical-k pairing (t<->2t, t+4<->2t+1): conflict-free.
// ---------------------------------------------------------------------------
#define GSTAGE 9344
#define GEMM_SMEM (3 * GSTAGE * 4)   // 112128 B

__device__ __forceinline__ void gemm_main(uint32_t* sm, uint32_t smb,
    const float* __restrict__ A, const float* __restrict__ B,
    int ldb, int n0, int row0, float acc[4][4][4])
{
    const int K = DM, KT = DM / 32;
    const int tid = threadIdx.x, lane = tid & 31, wid = tid >> 5;
    const int g = lane >> 2, t = lane & 3;
    const int m0 = (wid >> 2) * 64, nw = (wid & 3) * 32;

    // hoisted per-thread load addressing
    const int ar = tid >> 3, ac = (tid & 7) << 2;
    const int bk = tid >> 5, bn = (tid & 31) << 2;
    const uint32_t aDst = (ar * 40 + ac) * 4;
    const uint32_t bDst = (5120 + bk * 132 + bn) * 4;
    const float* aS = A + (size_t)(row0 + ar) * K + ac;
    const float* bS = B + (size_t)bk * ldb + n0 + bn;

    auto issue = [&](int slot, int kt) {
        uint32_t base = smb + slot * (GSTAGE * 4);
        const float* a = aS + kt * 32;
        const float* b = bS + (size_t)kt * 32 * ldb;
#pragma unroll
        for (int i = 0; i < 4; i++)
            cpa16(base + aDst + i * (32 * 40 * 4), a + (size_t)i * 32 * K);
#pragma unroll
        for (int i = 0; i < 4; i++)
            cpa16(base + bDst + i * (8 * 132 * 4), b + (size_t)i * 8 * ldb);
        CPA_COMMIT();
    };

#pragma unroll
    for (int mi = 0; mi < 4; mi++)
#pragma unroll
        for (int ni = 0; ni < 4; ni++)
#pragma unroll
            for (int r = 0; r < 4; r++) acc[mi][ni][r] = 0.f;

    issue(0, 0);
    issue(1, 1);

    for (int kt = 0; kt < KT; kt++) {
        if (kt + 1 < KT) asm volatile("cp.async.wait_group 1;" ::: "memory");
        else             asm volatile("cp.async.wait_group 0;" ::: "memory");
        __syncthreads();
        if (kt + 2 < KT) issue((kt + 2) % 3, kt + 2);

        uint32_t* st = sm + (kt % 3) * GSTAGE;
        uint32_t (*As)[40]  = (uint32_t(*)[40])st;
        uint32_t (*Bs)[132] = (uint32_t(*)[132])(st + 5120);
#pragma unroll
        for (int kk0 = 0; kk0 < 32; kk0 += 8) {
            uint32_t a[4][4], b[4][2];
#pragma unroll
            for (int mi = 0; mi < 4; mi++) {
                int rb = m0 + mi * 16 + g;
                uint2 av0 = *(const uint2*)&As[rb][kk0 + 2 * t];
                uint2 av1 = *(const uint2*)&As[rb + 8][kk0 + 2 * t];
                a[mi][0] = av0.x; a[mi][1] = av1.x; a[mi][2] = av0.y; a[mi][3] = av1.y;
            }
#pragma unroll
            for (int ni = 0; ni < 4; ni++) {
                b[ni][0] = Bs[kk0 + 2 * t][nw + ni * 8 + g];
                b[ni][1] = Bs[kk0 + 2 * t + 1][nw + ni * 8 + g];
            }
#pragma unroll
            for (int mi = 0; mi < 4; mi++)
#pragma unroll
                for (int ni = 0; ni < 4; ni++)
                    mma8(acc[mi][ni], a[mi], b[ni]);
        }
    }
}

// ---------------------------------------------------------------------------
// QKV projection + fused RoPE + permuted head-major stores (V transposed).
// grid (12, 32): bx 0..7 -> Q, 8..9 -> K, 10..11 -> V.
// ---------------------------------------------------------------------------
__global__ __launch_bounds__(256, 2) void qkv_gemm(
    const float* __restrict__ cs, const float* __restrict__ sn)
{
    extern __shared__ uint32_t sm[];
    uint32_t smb = (uint32_t)__cvta_generic_to_shared(sm);
    const int bx = blockIdx.x, row0 = blockIdx.y * 128;
    const int tid = threadIdx.x, lane = tid & 31, wid = tid >> 5;
    const int g = lane >> 2, t = lane & 3;
    const int m0 = (wid >> 2) * 64, nw = (wid & 3) * 32;
    float acc[4][4][4];

    if (bx < 8) {
        gemm_main(sm, smb, g_xr, g_wqr, DM, bx * 128, row0, acc);
#pragma unroll
        for (int mi = 0; mi < 4; mi++)
#pragma unroll
            for (int ni = 0; ni < 4; ni++) {
                int gc = bx * 128 + nw + ni * 8 + 2 * t;       // even original col
                int head = gc >> 6, j = (gc & 63) >> 1;
                int pj = perm8p(j), pj2 = perm8p(j + 32);
#pragma unroll
                for (int rr = 0; rr < 2; rr++) {
                    int row = row0 + m0 + mi * 16 + g + rr * 8;
                    int n = row & (SEQ - 1), bi = row >> 11;
                    float cv = cs[n * 32 + j], sv = sn[n * 32 + j];
                    float a0 = acc[mi][ni][rr * 2], a1 = acc[mi][ni][rr * 2 + 1];
                    size_t bp = ((size_t)(bi * NH + head) * SEQ + n) * HD;
                    g_q[bp + pj]  = r2f(f2tf((a0 * cv - a1 * sv) * QSC));
                    g_q[bp + pj2] = r2f(f2tf((a0 * sv + a1 * cv) * QSC));
                }
            }
    } else if (bx < 10) {
        gemm_main(sm, smb, g_xr, g_wkr, 256, (bx - 8) * 128, row0, acc);
#pragma unroll
        for (int mi = 0; mi < 4; mi++)
#pragma unroll
            for (int ni = 0; ni < 4; ni++) {
                int gc = (bx - 8) * 128 + nw + ni * 8 + 2 * t;
                int kvh = gc >> 6, j = (gc & 63) >> 1;
                int pj = perm8p(j), pj2 = perm8p(j + 32);
#pragma unroll
                for (int rr = 0; rr < 2; rr++) {
                    int row = row0 + m0 + mi * 16 + g + rr * 8;
                    int n = row & (SEQ - 1), bi = row >> 11;
                    float cv = cs[n * 32 + j], sv = sn[n * 32 + j];
                    float a0 = acc[mi][ni][rr * 2], a1 = acc[mi][ni][rr * 2 + 1];
                    size_t bp = ((size_t)(bi * NKV + kvh) * SEQ + n) * HD;
                    g_k[bp + pj]  = r2f(f2tf(a0 * cv - a1 * sv));
                    g_k[bp + pj2] = r2f(f2tf(a0 * sv + a1 * cv));
                }
            }
    } else {
        gemm_main(sm, smb, g_xr, g_wvr, 256, (bx - 10) * 128, row0, acc);
        // V: transposed store g_v[bh][d][n]
#pragma unroll
        for (int mi = 0; mi < 4; mi++)
#pragma unroll
            for (int ni = 0; ni < 4; ni++) {
                int gc = (bx - 10) * 128 + nw + ni * 8 + 2 * t;
                int kvh = gc >> 6, d = gc & 63;
#pragma unroll
                for (int rr = 0; rr < 2; rr++) {
                    int row = row0 + m0 + mi * 16 + g + rr * 8;
                    int n = row & (SEQ - 1), bi = row >> 11;
                    size_t hb = ((size_t)(bi * NKV + kvh) * HD);
                    g_v[(hb + d) * SEQ + n]     = r2f(f2tf(acc[mi][ni][rr * 2]));
                    g_v[(hb + d + 1) * SEQ + n] = r2f(f2tf(acc[mi][ni][rr * 2 + 1]));
                }
            }
    }
}

// ---------------------------------------------------------------------------
// Output projection
// ---------------------------------------------------------------------------
__global__ __launch_bounds__(256, 2) void out_gemm(float* __restrict__ out)
{
    extern __shared__ uint32_t sm[];
    uint32_t smb = (uint32_t)__cvta_generic_to_shared(sm);
    const int tid = threadIdx.x, lane = tid & 31, wid = tid >> 5;
    const int g = lane >> 2, t = lane & 3;
    const int m0 = (wid >> 2) * 64, nw = (wid & 3) * 32;
    const int n0 = blockIdx.x * 128, row0 = blockIdx.y * 128;
    float acc[4][4][4];
    gemm_main(sm, smb, g_attn, g_wor, DM, n0, row0, acc);
#pragma unroll
    for (int mi = 0; mi < 4; mi++) {
        int r = row0 + m0 + mi * 16 + g;
#pragma unroll
        for (int ni = 0; ni < 4; ni++) {
            int c = n0 + nw + ni * 8 + 2 * t;
            *(float2*)(out + (size_t)r * DM + c)       = make_float2(acc[mi][ni][0], acc[mi][ni][1]);
            *(float2*)(out + (size_t)(r + 8) * DM + c) = make_float2(acc[mi][ni][2], acc[mi][ni][3]);
        }
    }
}

// ---------------------------------------------------------------------------
// Flash attention: BM=256, 512 threads (16 warps), 1 CTA/SM, 3-stage KV ring
// (single __syncthreads per iter). V transposed (d x keys); softmax in exp2
// domain (Q pre-scaled by QSC at projection).
// Smem (u32): Qs[256*72]=18432 | 3 stages x (Ks[64*72]+Vt[64*72]=9216).
// Total 46080 words = 184320 B.
// ---------------------------------------------------------------------------
#define ATT_SMEM 184320

__device__ __forceinline__ void attn_issue_kv(uint32_t smb, int slot,
    const float* __restrict__ Kb, const float* __restrict__ Vb, int kt, int tid)
{
    uint32_t base = smb + (18432 + slot * 9216) * 4;
    const float* K0 = Kb + (size_t)kt * 64 * HD;
#pragma unroll
    for (int i = 0; i < 2; i++) {
        int c = tid + i * 512;
        int r = c >> 4, col = (c & 15) << 2;
        cpa16(base + (r * 72 + col) * 4, K0 + r * HD + col);
    }
#pragma unroll
    for (int i = 0; i < 2; i++) {
        int c = tid + i * 512;
        int r = c >> 4, col = (c & 15) << 2;
        cpa16(base + (4608 + r * 72 + col) * 4, Vb + (size_t)r * SEQ + kt * 64 + col);
    }
    CPA_COMMIT();
}

__global__ __launch_bounds__(512, 1) void attn_mma()
{
    extern __shared__ uint32_t sm[];
    uint32_t smb = (uint32_t)__cvta_generic_to_shared(sm);
    const int b = blockIdx.z, h = blockIdx.y;
    const int n0 = blockIdx.x * 256;
    const int kvh = h >> 2;
    const int tid = threadIdx.x, lane = tid & 31, wid = tid >> 5;  // wid 0..15
    const int g = lane >> 2, t = lane & 3;
    const int m0 = wid * 16;

    const float* Qb = g_q + ((size_t)(b * NH + h) * SEQ + n0) * HD;
    const float* Kb = g_k + ((size_t)(b * NKV + kvh) * SEQ) * HD;
    const float* Vb = g_v + ((size_t)(b * NKV + kvh) * HD) * SEQ;

    // Q tile: 256 rows x 64 words
#pragma unroll
    for (int i = 0; i < 8; i++) {
        int c = tid + i * 512;
        int r = c >> 4, col = (c & 15) << 2;
        cpa16(smb + (r * 72 + col) * 4, Qb + r * HD + col);
    }
    CPA_COMMIT();
    attn_issue_kv(smb, 0, Kb, Vb, 0, tid);
    attn_issue_kv(smb, 1, Kb, Vb, 1, tid);

    uint32_t* Qs = sm;
    float m0s = -1e30f, m1s = -1e30f, l0s = 0.f, l1s = 0.f;
    float o[8][4];
#pragma unroll
    for (int ni = 0; ni < 8; ni++)
#pragma unroll
        for (int r = 0; r < 4; r++) o[ni][r] = 0.f;

    const int KT = SEQ / 64;
    for (int kt = 0; kt < KT; kt++) {
        if (kt + 1 < KT) asm volatile("cp.async.wait_group 1;" ::: "memory");
        else             asm volatile("cp.async.wait_group 0;" ::: "memory");
        __syncthreads();    // single barrier: stage kt ready AND stage (kt+2)%3 free
        if (kt + 2 < KT) attn_issue_kv(smb, (kt + 2) % 3, Kb, Vb, kt + 2, tid);

        uint32_t* Ks = sm + 18432 + (kt % 3) * 9216;
        uint32_t* Vt = Ks + 4608;

        // S = Q * K^T (scores already in exp2 domain via QSC)
        float s[8][4];
#pragma unroll
        for (int ni = 0; ni < 8; ni++)
#pragma unroll
            for (int r = 0; r < 4; r++) s[ni][r] = 0.f;
#pragma unroll
        for (int kk = 0; kk < 8; kk++) {
            uint32_t a[4];
            uint2 p0 = *(const uint2*)&Qs[(m0 + g) * 72 + kk * 8 + 2 * t];
            uint2 p1 = *(const uint2*)&Qs[(m0 + g + 8) * 72 + kk * 8 + 2 * t];
            a[0] = p0.x; a[1] = p1.x; a[2] = p0.y; a[3] = p1.y;
#pragma unroll
            for (int ni = 0; ni < 8; ni++) {
                uint2 bv = *(const uint2*)&Ks[(ni * 8 + g) * 72 + kk * 8 + 2 * t];
                uint32_t bb[2] = {bv.x, bv.y};
                mma8(s[ni], a, bb);
            }
        }

        // online softmax (exp2 domain); thread owns keys 2t,2t+1 of rows m0+g, m0+g+8
        float mx0 = -1e30f, mx1 = -1e30f;
#pragma unroll
        for (int ni = 0; ni < 8; ni++) {
            mx0 = fmaxf(mx0, fmaxf(s[ni][0], s[ni][1]));
            mx1 = fmaxf(mx1, fmaxf(s[ni][2], s[ni][3]));
        }
        mx0 = fmaxf(mx0, __shfl_xor_sync(0xffffffffu, mx0, 1));
        mx0 = fmaxf(mx0, __shfl_xor_sync(0xffffffffu, mx0, 2));
        mx1 = fmaxf(mx1, __shfl_xor_sync(0xffffffffu, mx1, 1));
        mx1 = fmaxf(mx1, __shfl_xor_sync(0xffffffffu, mx1, 2));

        float mn0 = fmaxf(m0s, mx0), mn1 = fmaxf(m1s, mx1);
        float cor0 = ex2f(m0s - mn0), cor1 = ex2f(m1s - mn1);
        m0s = mn0; m1s = mn1;

        float rs0 = 0.f, rs1 = 0.f;
#pragma unroll
        for (int ni = 0; ni < 8; ni++) {
            s[ni][0] = ex2f(s[ni][0] - mn0);
            s[ni][1] = ex2f(s[ni][1] - mn0);
            s[ni][2] = ex2f(s[ni][2] - mn1);
            s[ni][3] = ex2f(s[ni][3] - mn1);
            rs0 += s[ni][0] + s[ni][1];
            rs1 += s[ni][2] + s[ni][3];
        }
        rs0 += __shfl_xor_sync(0xffffffffu, rs0, 1);
        rs0 += __shfl_xor_sync(0xffffffffu, rs0, 2);
        rs1 += __shfl_xor_sync(0xffffffffu, rs1, 1);
        rs1 += __shfl_xor_sync(0xffffffffu, rs1, 2);
        l0s = l0s * cor0 + rs0;
        l1s = l1s * cor1 + rs1;

#pragma unroll
        for (int ni = 0; ni < 8; ni++) {
            o[ni][0] *= cor0; o[ni][1] *= cor0;
            o[ni][2] *= cor1; o[ni][3] *= cor1;
        }

        // O += P * V : A-frag on the fly (keys 2t<->k=t, 2t+1<->k=t+4),
        // B-frag single LDS.64 from Vt row (d), cols 2t,2t+1.
#pragma unroll
        for (int kk = 0; kk < 8; kk++) {
            uint32_t a[4];
            a[0] = f2tf(s[kk][0]);
            a[1] = f2tf(s[kk][2]);
            a[2] = f2tf(s[kk][1]);
            a[3] = f2tf(s[kk][3]);
#pragma unroll
            for (int ni = 0; ni < 8; ni++) {
                uint2 bv = *(const uint2*)&Vt[(ni * 8 + g) * 72 + kk * 8 + 2 * t];
                uint32_t bb[2] = {bv.x, bv.y};
                mma8(o[ni], a, bb);
            }
        }
    }

    // epilogue: normalize, round to tf32, write (b,n,1024) for out_gemm
    float inv0 = 1.f / l0s, inv1 = 1.f / l1s;
    size_t r0 = (size_t)b * SEQ + n0 + m0 + g;
#pragma unroll
    for (int ni = 0; ni < 8; ni++) {
        int col = h * HD + ni * 8 + 2 * t;
        *(float2*)&g_attn[r0 * DM + col] =
            make_float2(r2f(f2tf(o[ni][0] * inv0)), r2f(f2tf(o[ni][1] * inv0)));
        *(float2*)&g_attn[(r0 + 8) * DM + col] =
            make_float2(r2f(f2tf(o[ni][2] * inv1)), r2f(f2tf(o[ni][3] * inv1)));
    }
}

// ---------------------------------------------------------------------------
extern "C" void kernel_launch(void* const* d_in, const int* in_sizes, int n_in,
                              void* d_out, int out_size)
{
    const float* x  = (const float*)d_in[0];
    const float* cs = (const float*)d_in[1];
    const float* sn = (const float*)d_in[2];
    const float* Wq = (const float*)d_in[3];
    const float* Wk = (const float*)d_in[4];
    const float* Wv = (const float*)d_in[5];
    const float* Wo = (const float*)d_in[6];
    float* out = (float*)d_out;
    (void)in_sizes; (void)n_in; (void)out_size;

    cudaFuncSetAttribute(qkv_gemm, cudaFuncAttributeMaxDynamicSharedMemorySize, GEMM_SMEM);
    cudaFuncSetAttribute(out_gemm, cudaFuncAttributeMaxDynamicSharedMemorySize, GEMM_SMEM);
    cudaFuncSetAttribute(attn_mma, cudaFuncAttributeMaxDynamicSharedMemorySize, ATT_SMEM);

    // 1) round x + weights onto the tf32 grid
    prep_round<<<6656, 256>>>(x, Wq, Wk, Wv, Wo);

    // 2) QKV projections + fused RoPE + permuted head-major stores
    qkv_gemm<<<dim3(12, 32), 256, GEMM_SMEM>>>(cs, sn);

    // 3) attention: grid (8 q-tiles of 256, 16 heads, 2 batch)
    attn_mma<<<dim3(SEQ / 256, NH, BB), 512, ATT_SMEM>>>();

    // 4) output projection
    out_gemm<<<dim3(8, 32), 256, GEMM_SMEM>>>(out);
}

// round 7
// speedup vs baseline: 4.2463x; 1.0032x over previous
#include <cuda_runtime.h>
#include <cstdint>

#define NH   16
#define NKV  4
#define HD   64
#define DM   1024
#define BB   2
#define SEQ  2048
#define MROWS (BB*SEQ)   // 4096

// Q pre-scale: HD^-0.5 * log2(e)  (softmax done in exp2 domain)
#define QSC 0.18033688011112042f

// ---------------------------------------------------------------------------
// Scratch (allocation-free device globals)
// ---------------------------------------------------------------------------
__device__ float g_xr [(size_t)MROWS * DM];       // tf32-rounded x
__device__ float g_wqr[(size_t)DM * DM];
__device__ float g_wkr[(size_t)DM * 256];
__device__ float g_wvr[(size_t)DM * 256];
__device__ float g_wor[(size_t)DM * DM];
__device__ float g_q  [(size_t)BB * NH  * SEQ * HD];  // head-major, d-permuted, *QSC, rope'd
__device__ float g_k  [(size_t)BB * NKV * SEQ * HD];  // head-major, d-permuted, rope'd
__device__ float g_v  [(size_t)BB * NKV * HD * SEQ];  // head-major TRANSPOSED: [d][seq]
__device__ float g_attn[(size_t)MROWS * DM];          // (b,n,1024), tf32-rounded

// ---------------------------------------------------------------------------
// helpers
// ---------------------------------------------------------------------------
__device__ __forceinline__ uint32_t f2tf(float f) {
    uint32_t u;
    asm("cvt.rna.tf32.f32 %0, %1;" : "=r"(u) : "f"(f));
    return u;
}
__device__ __forceinline__ float r2f(uint32_t u) { return __uint_as_float(u); }

__device__ __forceinline__ float ex2f(float x) {
    float r;
    asm("ex2.approx.ftz.f32 %0, %1;" : "=f"(r) : "f"(x));
    return r;
}

// position of head-col j under the within-8-group d-permute (for Q/K S-gemm)
__device__ __forceinline__ int perm8p(int j) {
    int u = j & 7;
    return (j & ~7) + ((u < 4) ? 2 * u : 2 * (u - 4) + 1);
}

__device__ __forceinline__ void mma8(float c[4], const uint32_t a[4], const uint32_t b[2]) {
    asm volatile(
        "mma.sync.aligned.m16n8k8.row.col.f32.tf32.tf32.f32 "
        "{%0,%1,%2,%3},{%4,%5,%6,%7},{%8,%9},{%0,%1,%2,%3};"
        : "+f"(c[0]), "+f"(c[1]), "+f"(c[2]), "+f"(c[3])
        : "r"(a[0]), "r"(a[1]), "r"(a[2]), "r"(a[3]), "r"(b[0]), "r"(b[1]));
}

__device__ __forceinline__ void cpa16(uint32_t dst, const void* src) {
    asm volatile("cp.async.cg.shared.global [%0], [%1], 16;" :: "r"(dst), "l"(src) : "memory");
}
#define CPA_COMMIT() asm volatile("cp.async.commit_group;" ::: "memory")

// ---------------------------------------------------------------------------
// Pre-pass: round x + weights to the tf32 grid (then mma can eat them raw).
// ---------------------------------------------------------------------------
__global__ void prep_round(const float* __restrict__ x,  const float* __restrict__ Wq,
                           const float* __restrict__ Wk, const float* __restrict__ Wv,
                           const float* __restrict__ Wo)
{
    size_t i = (size_t)blockIdx.x * 256 + threadIdx.x;   // float4 index
    const float* src; float* dst; size_t off;
    if      (i < 1048576) { src = x;  dst = g_xr;  off = i; }
    else if (i < 1310720) { src = Wq; dst = g_wqr; off = i - 1048576; }
    else if (i < 1376256) { src = Wk; dst = g_wkr; off = i - 1310720; }
    else if (i < 1441792) { src = Wv; dst = g_wvr; off = i - 1376256; }
    else                  { src = Wo; dst = g_wor; off = i - 1441792; }
    float4 v = ((const float4*)src)[off];
    v.x = r2f(f2tf(v.x)); v.y = r2f(f2tf(v.y));
    v.z = r2f(f2tf(v.z)); v.w = r2f(f2tf(v.w));
    ((float4*)dst)[off] = v;
}

// ---------------------------------------------------------------------------
// cp.async 3-stage GEMM: 128x128 tile, kstep 32, 256 threads, warp tile 64x32.
// Stage: As[128][40] (5120 w) + Bs[32][132] (4224 w) = 9344 words.
// ---------------------------------------------------------------------------
#define GSTAGE 9344
#define GEMM_SMEM (3 * GSTAGE * 4)   // 112128 B

__device__ __forceinline__ void gemm_main(uint32_t* sm, uint32_t smb,
    const float* __restrict__ A, const float* __restrict__ B,
    int ldb, int n0, int row0, float acc[4][4][4])
{
    const int K = DM, KT = DM / 32;
    const int tid = threadIdx.x, lane = tid & 31, wid = tid >> 5;
    const int g = lane >> 2, t = lane & 3;
    const int m0 = (wid >> 2) * 64, nw = (wid & 3) * 32;

    const int ar = tid >> 3, ac = (tid & 7) << 2;
    const int bk = tid >> 5, bn = (tid & 31) << 2;
    const uint32_t aDst = (ar * 40 + ac) * 4;
    const uint32_t bDst = (5120 + bk * 132 + bn) * 4;
    const float* aS = A + (size_t)(row0 + ar) * K + ac;
    const float* bS = B + (size_t)bk * ldb + n0 + bn;

    auto issue = [&](int slot, int kt) {
        uint32_t base = smb + slot * (GSTAGE * 4);
        const float* a = aS + kt * 32;
        const float* b = bS + (size_t)kt * 32 * ldb;
#pragma unroll
        for (int i = 0; i < 4; i++)
            cpa16(base + aDst + i * (32 * 40 * 4), a + (size_t)i * 32 * K);
#pragma unroll
        for (int i = 0; i < 4; i++)
            cpa16(base + bDst + i * (8 * 132 * 4), b + (size_t)i * 8 * ldb);
        CPA_COMMIT();
    };

#pragma unroll
    for (int mi = 0; mi < 4; mi++)
#pragma unroll
        for (int ni = 0; ni < 4; ni++)
#pragma unroll
            for (int r = 0; r < 4; r++) acc[mi][ni][r] = 0.f;

    issue(0, 0);
    issue(1, 1);

    for (int kt = 0; kt < KT; kt++) {
        if (kt + 1 < KT) asm volatile("cp.async.wait_group 1;" ::: "memory");
        else             asm volatile("cp.async.wait_group 0;" ::: "memory");
        __syncthreads();
        if (kt + 2 < KT) issue((kt + 2) % 3, kt + 2);

        uint32_t* st = sm + (kt % 3) * GSTAGE;
        uint32_t (*As)[40]  = (uint32_t(*)[40])st;
        uint32_t (*Bs)[132] = (uint32_t(*)[132])(st + 5120);
#pragma unroll
        for (int kk0 = 0; kk0 < 32; kk0 += 8) {
            uint32_t a[4][4], b[4][2];
#pragma unroll
            for (int mi = 0; mi < 4; mi++) {
                int rb = m0 + mi * 16 + g;
                uint2 av0 = *(const uint2*)&As[rb][kk0 + 2 * t];
                uint2 av1 = *(const uint2*)&As[rb + 8][kk0 + 2 * t];
                a[mi][0] = av0.x; a[mi][1] = av1.x; a[mi][2] = av0.y; a[mi][3] = av1.y;
            }
#pragma unroll
            for (int ni = 0; ni < 4; ni++) {
                b[ni][0] = Bs[kk0 + 2 * t][nw + ni * 8 + g];
                b[ni][1] = Bs[kk0 + 2 * t + 1][nw + ni * 8 + g];
            }
#pragma unroll
            for (int mi = 0; mi < 4; mi++)
#pragma unroll
                for (int ni = 0; ni < 4; ni++)
                    mma8(acc[mi][ni], a[mi], b[ni]);
        }
    }
}

// ---------------------------------------------------------------------------
// QKV projection + fused RoPE + permuted head-major stores (V transposed).
// ---------------------------------------------------------------------------
__global__ __launch_bounds__(256, 2) void qkv_gemm(
    const float* __restrict__ cs, const float* __restrict__ sn)
{
    extern __shared__ uint32_t sm[];
    uint32_t smb = (uint32_t)__cvta_generic_to_shared(sm);
    const int bx = blockIdx.x, row0 = blockIdx.y * 128;
    const int tid = threadIdx.x, lane = tid & 31, wid = tid >> 5;
    const int g = lane >> 2, t = lane & 3;
    const int m0 = (wid >> 2) * 64, nw = (wid & 3) * 32;
    float acc[4][4][4];

    if (bx < 8) {
        gemm_main(sm, smb, g_xr, g_wqr, DM, bx * 128, row0, acc);
#pragma unroll
        for (int mi = 0; mi < 4; mi++)
#pragma unroll
            for (int ni = 0; ni < 4; ni++) {
                int gc = bx * 128 + nw + ni * 8 + 2 * t;       // even original col
                int head = gc >> 6, j = (gc & 63) >> 1;
                int pj = perm8p(j), pj2 = perm8p(j + 32);
#pragma unroll
                for (int rr = 0; rr < 2; rr++) {
                    int row = row0 + m0 + mi * 16 + g + rr * 8;
                    int n = row & (SEQ - 1), bi = row >> 11;
                    float cv = cs[n * 32 + j], sv = sn[n * 32 + j];
                    float a0 = acc[mi][ni][rr * 2], a1 = acc[mi][ni][rr * 2 + 1];
                    size_t bp = ((size_t)(bi * NH + head) * SEQ + n) * HD;
                    g_q[bp + pj]  = r2f(f2tf((a0 * cv - a1 * sv) * QSC));
                    g_q[bp + pj2] = r2f(f2tf((a0 * sv + a1 * cv) * QSC));
                }
            }
    } else if (bx < 10) {
        gemm_main(sm, smb, g_xr, g_wkr, 256, (bx - 8) * 128, row0, acc);
#pragma unroll
        for (int mi = 0; mi < 4; mi++)
#pragma unroll
            for (int ni = 0; ni < 4; ni++) {
                int gc = (bx - 8) * 128 + nw + ni * 8 + 2 * t;
                int kvh = gc >> 6, j = (gc & 63) >> 1;
                int pj = perm8p(j), pj2 = perm8p(j + 32);
#pragma unroll
                for (int rr = 0; rr < 2; rr++) {
                    int row = row0 + m0 + mi * 16 + g + rr * 8;
                    int n = row & (SEQ - 1), bi = row >> 11;
                    float cv = cs[n * 32 + j], sv = sn[n * 32 + j];
                    float a0 = acc[mi][ni][rr * 2], a1 = acc[mi][ni][rr * 2 + 1];
                    size_t bp = ((size_t)(bi * NKV + kvh) * SEQ + n) * HD;
                    g_k[bp + pj]  = r2f(f2tf(a0 * cv - a1 * sv));
                    g_k[bp + pj2] = r2f(f2tf(a0 * sv + a1 * cv));
                }
            }
    } else {
        gemm_main(sm, smb, g_xr, g_wvr, 256, (bx - 10) * 128, row0, acc);
#pragma unroll
        for (int mi = 0; mi < 4; mi++)
#pragma unroll
            for (int ni = 0; ni < 4; ni++) {
                int gc = (bx - 10) * 128 + nw + ni * 8 + 2 * t;
                int kvh = gc >> 6, d = gc & 63;
#pragma unroll
                for (int rr = 0; rr < 2; rr++) {
                    int row = row0 + m0 + mi * 16 + g + rr * 8;
                    int n = row & (SEQ - 1), bi = row >> 11;
                    size_t hb = ((size_t)(bi * NKV + kvh) * HD);
                    g_v[(hb + d) * SEQ + n]     = r2f(f2tf(acc[mi][ni][rr * 2]));
                    g_v[(hb + d + 1) * SEQ + n] = r2f(f2tf(acc[mi][ni][rr * 2 + 1]));
                }
            }
    }
}

// ---------------------------------------------------------------------------
// Output projection
// ---------------------------------------------------------------------------
__global__ __launch_bounds__(256, 2) void out_gemm(float* __restrict__ out)
{
    extern __shared__ uint32_t sm[];
    uint32_t smb = (uint32_t)__cvta_generic_to_shared(sm);
    const int tid = threadIdx.x, lane = tid & 31, wid = tid >> 5;
    const int g = lane >> 2, t = lane & 3;
    const int m0 = (wid >> 2) * 64, nw = (wid & 3) * 32;
    const int n0 = blockIdx.x * 128, row0 = blockIdx.y * 128;
    float acc[4][4][4];
    gemm_main(sm, smb, g_attn, g_wor, DM, n0, row0, acc);
#pragma unroll
    for (int mi = 0; mi < 4; mi++) {
        int r = row0 + m0 + mi * 16 + g;
#pragma unroll
        for (int ni = 0; ni < 4; ni++) {
            int c = n0 + nw + ni * 8 + 2 * t;
            *(float2*)(out + (size_t)r * DM + c)       = make_float2(acc[mi][ni][0], acc[mi][ni][1]);
            *(float2*)(out + (size_t)(r + 8) * DM + c) = make_float2(acc[mi][ni][2], acc[mi][ni][3]);
        }
    }
}

// ---------------------------------------------------------------------------
// Flash attention: BM=256, 512 threads (16 warps), 1 CTA/SM, 4-stage KV ring.
// Warp-group phase stagger: group A (warps 0-7, rows 0-127) runs
// S->softmax->PV each iter; group B (warps 8-15, rows 128-255) runs
// softmax(prev)->PV(prev)->S(cur), i.e. shifted half an iteration, so the
// tensor pipe is fed by one group while the other does MUFU/FMA softmax.
// Smem (u32): Qs[256*72]=18432 | 4 stages x (Ks[64*72]+Vt[64*72]=9216)
// = 55296 words = 221184 B.
// ---------------------------------------------------------------------------
#define ATT_SMEM 221184

__device__ __forceinline__ void attn_issue_kv(uint32_t smb, int slot,
    const float* __restrict__ Kb, const float* __restrict__ Vb, int kt, int tid)
{
    uint32_t base = smb + (18432 + slot * 9216) * 4;
    const float* K0 = Kb + (size_t)kt * 64 * HD;
#pragma unroll
    for (int i = 0; i < 2; i++) {
        int c = tid + i * 512;
        int r = c >> 4, col = (c & 15) << 2;
        cpa16(base + (r * 72 + col) * 4, K0 + r * HD + col);
    }
#pragma unroll
    for (int i = 0; i < 2; i++) {
        int c = tid + i * 512;
        int r = c >> 4, col = (c & 15) << 2;
        cpa16(base + (4608 + r * 72 + col) * 4, Vb + (size_t)r * SEQ + kt * 64 + col);
    }
    CPA_COMMIT();
}

// S = Q*K^T for this warp's 16 rows x 64 keys (exp2 domain via QSC prescale)
__device__ __forceinline__ void s_gemm(float s[8][4],
    const uint32_t* Qs, const uint32_t* Ks, int m0, int g, int t)
{
#pragma unroll
    for (int ni = 0; ni < 8; ni++)
#pragma unroll
        for (int r = 0; r < 4; r++) s[ni][r] = 0.f;
#pragma unroll
    for (int kk = 0; kk < 8; kk++) {
        uint32_t a[4];
        uint2 p0 = *(const uint2*)&Qs[(m0 + g) * 72 + kk * 8 + 2 * t];
        uint2 p1 = *(const uint2*)&Qs[(m0 + g + 8) * 72 + kk * 8 + 2 * t];
        a[0] = p0.x; a[1] = p1.x; a[2] = p0.y; a[3] = p1.y;
#pragma unroll
        for (int ni = 0; ni < 8; ni++) {
            uint2 bv = *(const uint2*)&Ks[(ni * 8 + g) * 72 + kk * 8 + 2 * t];
            uint32_t bb[2] = {bv.x, bv.y};
            mma8(s[ni], a, bb);
        }
    }
}

// online-softmax update on s + rescale o + O += P*V from Vt stage
__device__ __forceinline__ void softmax_pv(float s[8][4], float o[8][4],
    float& m0s, float& m1s, float& l0s, float& l1s,
    const uint32_t* Vt, int g, int t)
{
    float mx0 = -1e30f, mx1 = -1e30f;
#pragma unroll
    for (int ni = 0; ni < 8; ni++) {
        mx0 = fmaxf(mx0, fmaxf(s[ni][0], s[ni][1]));
        mx1 = fmaxf(mx1, fmaxf(s[ni][2], s[ni][3]));
    }
    mx0 = fmaxf(mx0, __shfl_xor_sync(0xffffffffu, mx0, 1));
    mx0 = fmaxf(mx0, __shfl_xor_sync(0xffffffffu, mx0, 2));
    mx1 = fmaxf(mx1, __shfl_xor_sync(0xffffffffu, mx1, 1));
    mx1 = fmaxf(mx1, __shfl_xor_sync(0xffffffffu, mx1, 2));

    float mn0 = fmaxf(m0s, mx0), mn1 = fmaxf(m1s, mx1);
    float cor0 = ex2f(m0s - mn0), cor1 = ex2f(m1s - mn1);
    m0s = mn0; m1s = mn1;

    float rs0 = 0.f, rs1 = 0.f;
#pragma unroll
    for (int ni = 0; ni < 8; ni++) {
        s[ni][0] = ex2f(s[ni][0] - mn0);
        s[ni][1] = ex2f(s[ni][1] - mn0);
        s[ni][2] = ex2f(s[ni][2] - mn1);
        s[ni][3] = ex2f(s[ni][3] - mn1);
        rs0 += s[ni][0] + s[ni][1];
        rs1 += s[ni][2] + s[ni][3];
    }
    rs0 += __shfl_xor_sync(0xffffffffu, rs0, 1);
    rs0 += __shfl_xor_sync(0xffffffffu, rs0, 2);
    rs1 += __shfl_xor_sync(0xffffffffu, rs1, 1);
    rs1 += __shfl_xor_sync(0xffffffffu, rs1, 2);
    l0s = l0s * cor0 + rs0;
    l1s = l1s * cor1 + rs1;

#pragma unroll
    for (int ni = 0; ni < 8; ni++) {
        o[ni][0] *= cor0; o[ni][1] *= cor0;
        o[ni][2] *= cor1; o[ni][3] *= cor1;
    }
#pragma unroll
    for (int kk = 0; kk < 8; kk++) {
        uint32_t a[4];
        a[0] = f2tf(s[kk][0]);
        a[1] = f2tf(s[kk][2]);
        a[2] = f2tf(s[kk][1]);
        a[3] = f2tf(s[kk][3]);
#pragma unroll
        for (int ni = 0; ni < 8; ni++) {
            uint2 bv = *(const uint2*)&Vt[(ni * 8 + g) * 72 + kk * 8 + 2 * t];
            uint32_t bb[2] = {bv.x, bv.y};
            mma8(o[ni], a, bb);
        }
    }
}

__global__ __launch_bounds__(512, 1) void attn_mma()
{
    extern __shared__ uint32_t sm[];
    uint32_t smb = (uint32_t)__cvta_generic_to_shared(sm);
    const int b = blockIdx.z, h = blockIdx.y;
    const int n0 = blockIdx.x * 256;
    const int kvh = h >> 2;
    const int tid = threadIdx.x, lane = tid & 31, wid = tid >> 5;  // wid 0..15
    const int g = lane >> 2, t = lane & 3;
    const int m0 = wid * 16;
    const bool grpB = (wid >= 8);

    const float* Qb = g_q + ((size_t)(b * NH + h) * SEQ + n0) * HD;
    const float* Kb = g_k + ((size_t)(b * NKV + kvh) * SEQ) * HD;
    const float* Vb = g_v + ((size_t)(b * NKV + kvh) * HD) * SEQ;

    // Q tile: 256 rows x 64 words (own commit group)
#pragma unroll
    for (int i = 0; i < 8; i++) {
        int c = tid + i * 512;
        int r = c >> 4, col = (c & 15) << 2;
        cpa16(smb + (r * 72 + col) * 4, Qb + r * HD + col);
    }
    CPA_COMMIT();
    attn_issue_kv(smb, 0, Kb, Vb, 0, tid);
    attn_issue_kv(smb, 1, Kb, Vb, 1, tid);

    uint32_t* Qs = sm;
    float m0s = -1e30f, m1s = -1e30f, l0s = 0.f, l1s = 0.f;
    float s[8][4], o[8][4];
#pragma unroll
    for (int ni = 0; ni < 8; ni++)
#pragma unroll
        for (int r = 0; r < 4; r++) o[ni][r] = 0.f;

    const int KT = SEQ / 64;
    for (int kt = 0; kt < KT; kt++) {
        // ensure stage kt loaded (pending = {kt, kt+1} at steady state)
        if (kt + 1 < KT) asm volatile("cp.async.wait_group 1;" ::: "memory");
        else             asm volatile("cp.async.wait_group 0;" ::: "memory");
        __syncthreads();   // stage kt ready for all; slot (kt+2)%4 fully consumed
        if (kt + 2 < KT) attn_issue_kv(smb, (kt + 2) & 3, Kb, Vb, kt + 2, tid);

        uint32_t* KsCur = sm + 18432 + (kt & 3) * 9216;
        if (!grpB) {
            // group A: mma first, scalars second
            s_gemm(s, Qs, KsCur, m0, g, t);
            softmax_pv(s, o, m0s, m1s, l0s, l1s, KsCur + 4608, g, t);
        } else {
            // group B: finish previous block (scalars first), then mma
            if (kt > 0) {
                uint32_t* VtPrev = sm + 18432 + ((kt - 1) & 3) * 9216 + 4608;
                softmax_pv(s, o, m0s, m1s, l0s, l1s, VtPrev, g, t);
            }
            s_gemm(s, Qs, KsCur, m0, g, t);
        }
    }
    if (grpB) {
        // group B tail: last block's softmax + PV
        uint32_t* VtLast = sm + 18432 + ((KT - 1) & 3) * 9216 + 4608;
        softmax_pv(s, o, m0s, m1s, l0s, l1s, VtLast, g, t);
    }

    // epilogue: normalize, round to tf32, write (b,n,1024) for out_gemm
    float inv0 = 1.f / l0s, inv1 = 1.f / l1s;
    size_t r0 = (size_t)b * SEQ + n0 + m0 + g;
#pragma unroll
    for (int ni = 0; ni < 8; ni++) {
        int col = h * HD + ni * 8 + 2 * t;
        *(float2*)&g_attn[r0 * DM + col] =
            make_float2(r2f(f2tf(o[ni][0] * inv0)), r2f(f2tf(o[ni][1] * inv0)));
        *(float2*)&g_attn[(r0 + 8) * DM + col] =
            make_float2(r2f(f2tf(o[ni][2] * inv1)), r2f(f2tf(o[ni][3] * inv1)));
    }
}

// ---------------------------------------------------------------------------
extern "C" void kernel_launch(void* const* d_in, const int* in_sizes, int n_in,
                              void* d_out, int out_size)
{
    const float* x  = (const float*)d_in[0];
    const float* cs = (const float*)d_in[1];
    const float* sn = (const float*)d_in[2];
    const float* Wq = (const float*)d_in[3];
    const float* Wk = (const float*)d_in[4];
    const float* Wv = (const float*)d_in[5];
    const float* Wo = (const float*)d_in[6];
    float* out = (float*)d_out;
    (void)in_sizes; (void)n_in; (void)out_size;

    cudaFuncSetAttribute(qkv_gemm, cudaFuncAttributeMaxDynamicSharedMemorySize, GEMM_SMEM);
    cudaFuncSetAttribute(out_gemm, cudaFuncAttributeMaxDynamicSharedMemorySize, GEMM_SMEM);
    cudaFuncSetAttribute(attn_mma, cudaFuncAttributeMaxDynamicSharedMemorySize, ATT_SMEM);

    // 1) round x + weights onto the tf32 grid
    prep_round<<<6656, 256>>>(x, Wq, Wk, Wv, Wo);

    // 2) QKV projections + fused RoPE + permuted head-major stores
    qkv_gemm<<<dim3(12, 32), 256, GEMM_SMEM>>>(cs, sn);

    // 3) attention: grid (8 q-tiles of 256, 16 heads, 2 batch)
    attn_mma<<<dim3(SEQ / 256, NH, BB), 512, ATT_SMEM>>>();

    // 4) output projection
    out_gemm<<<dim3(8, 32), 256, GEMM_SMEM>>>(out);
}